// round 1
// baseline (speedup 1.0000x reference)
#include <cuda_runtime.h>
#include <cuda_bf16.h>

// Problem constants
#define Bz   2
#define SEQ  2048
#define CC   768
#define HH   12
#define DH   64
#define MM   (Bz*SEQ)        // 4096
#define C3   (3*CC)          // 2304

// Scratch (no cudaMalloc allowed)
__device__ float g_qkv[(size_t)MM * C3];   // [B*N, 3*C]  (3, H, Dh) packed in cols
__device__ float g_att[(size_t)MM * CC];   // attention output [B*N, C] (h,d packed)

// ---------------------------------------------------------------------------
// SGEMM: C = A(MxK) * B(KxN) + bias(N), all row-major. 128x128x8 tile,
// 256 threads, 8x8 per thread. M%128==0, N%128==0, K%8==0 assumed.
// ---------------------------------------------------------------------------
__global__ __launch_bounds__(256) void sgemm128(
    const float* __restrict__ A, const float* __restrict__ Bm,
    const float* __restrict__ bias, float* __restrict__ Cm,
    int M, int Nn, int K)
{
    __shared__ float As[8][128];
    __shared__ float Bs[8][128];

    const int tid = threadIdx.x;
    const int tx = tid & 15;          // 0..15  -> col group
    const int ty = tid >> 4;          // 0..15  -> row group
    const int row0 = blockIdx.y * 128;
    const int col0 = blockIdx.x * 128;

    const int aRow = tid >> 1;            // 0..127
    const int aCol = (tid & 1) * 4;       // 0 or 4
    const int bRow = tid >> 5;            // 0..7
    const int bCol = (tid & 31) * 4;      // 0..124

    float acc[8][8];
    #pragma unroll
    for (int i = 0; i < 8; i++)
        #pragma unroll
        for (int j = 0; j < 8; j++) acc[i][j] = 0.f;

    for (int k0 = 0; k0 < K; k0 += 8) {
        float4 av = *(const float4*)(A + (size_t)(row0 + aRow) * K + k0 + aCol);
        As[aCol + 0][aRow] = av.x;
        As[aCol + 1][aRow] = av.y;
        As[aCol + 2][aRow] = av.z;
        As[aCol + 3][aRow] = av.w;
        *(float4*)&Bs[bRow][bCol] =
            *(const float4*)(Bm + (size_t)(k0 + bRow) * Nn + col0 + bCol);
        __syncthreads();

        #pragma unroll
        for (int kk = 0; kk < 8; kk++) {
            float a[8], b[8];
            *(float4*)(a)     = *(float4*)&As[kk][ty * 8];
            *(float4*)(a + 4) = *(float4*)&As[kk][ty * 8 + 4];
            *(float4*)(b)     = *(float4*)&Bs[kk][tx * 8];
            *(float4*)(b + 4) = *(float4*)&Bs[kk][tx * 8 + 4];
            #pragma unroll
            for (int i = 0; i < 8; i++)
                #pragma unroll
                for (int j = 0; j < 8; j++)
                    acc[i][j] += a[i] * b[j];
        }
        __syncthreads();
    }

    #pragma unroll
    for (int i = 0; i < 8; i++) {
        const int r = row0 + ty * 8 + i;
        #pragma unroll
        for (int j4 = 0; j4 < 2; j4++) {
            const int c = col0 + tx * 8 + j4 * 4;
            float4 o;
            o.x = acc[i][j4 * 4 + 0] + bias[c + 0];
            o.y = acc[i][j4 * 4 + 1] + bias[c + 1];
            o.z = acc[i][j4 * 4 + 2] + bias[c + 2];
            o.w = acc[i][j4 * 4 + 3] + bias[c + 3];
            *(float4*)(Cm + (size_t)r * Nn + c) = o;
        }
    }
}

// ---------------------------------------------------------------------------
// Fused RMSNorm + RoPE on q and k slices of g_qkv (in place).
// One warp per (b*n, h, which) row of 64 elements. 2*B*N*H rows total.
// ---------------------------------------------------------------------------
__global__ __launch_bounds__(256) void rmsnorm_rope(
    const float* __restrict__ cosb, const float* __restrict__ sinb,
    const float* __restrict__ qn_w, const float* __restrict__ kn_w)
{
    const int warp = (blockIdx.x * blockDim.x + threadIdx.x) >> 5;
    const int lane = threadIdx.x & 31;
    // warp in [0, 2*B*N*H)
    const int which = warp & 1;                 // 0 -> q, 1 -> k
    const int h     = (warp >> 1) % HH;
    const int bn    = warp / (2 * HH);          // 0..B*N-1
    const int n     = bn & (SEQ - 1);

    const float* w = which ? kn_w : qn_w;
    float* p = g_qkv + (size_t)bn * C3 + which * CC + h * DH;

    float2 v = *(float2*)(p + 2 * lane);
    float ss = v.x * v.x + v.y * v.y;
    #pragma unroll
    for (int o = 16; o; o >>= 1) ss += __shfl_xor_sync(0xffffffffu, ss, o);
    const float inv = rsqrtf(ss * (1.0f / (float)DH) + 1e-6f);

    float x0 = v.x * inv * w[2 * lane];
    float x1 = v.y * inv * w[2 * lane + 1];
    const float c = cosb[n * (DH / 2) + lane];
    const float s = sinb[n * (DH / 2) + lane];
    float2 r;
    r.x = x0 * c - x1 * s;
    r.y = x0 * s + x1 * c;
    *(float2*)(p + 2 * lane) = r;
}

// ---------------------------------------------------------------------------
// Flash attention (fp32, online softmax). Block = 64 threads, one thread per
// query row. K/V tiles of 32 rows staged in smem; broadcast float4 reads.
// grid = (B*H, SEQ/64)
// ---------------------------------------------------------------------------
__global__ __launch_bounds__(64) void flash_attn()
{
    const int bh = blockIdx.x;
    const int b = bh / HH, h = bh % HH;
    const int qrow = blockIdx.y * 64 + threadIdx.x;
    const int t = threadIdx.x;

    const float* base = g_qkv + (size_t)b * SEQ * C3;
    const float* Qp = base + (size_t)qrow * C3 + h * DH;

    __shared__ float Ks[32][DH];
    __shared__ float Vs[32][DH];

    float4 q[16], o[16];
    #pragma unroll
    for (int i = 0; i < 16; i++) {
        q[i] = *(const float4*)(Qp + 4 * i);
        o[i] = make_float4(0.f, 0.f, 0.f, 0.f);
    }
    float m = -1e30f, l = 0.f;
    const float scale = 0.125f;   // Dh^-0.5

    for (int kt = 0; kt < SEQ; kt += 32) {
        // cooperative load of K and V tiles (32 x 64 each)
        #pragma unroll
        for (int idx = t; idx < 512; idx += 64) {
            const int rr = idx >> 4, c4 = (idx & 15) * 4;
            const float* kp = base + (size_t)(kt + rr) * C3 + CC + h * DH + c4;
            *(float4*)&Ks[rr][c4] = *(const float4*)kp;
            *(float4*)&Vs[rr][c4] = *(const float4*)(kp + CC);
        }
        __syncthreads();

        float s[32];
        float tmax = -1e30f;
        #pragma unroll
        for (int j = 0; j < 32; j++) {
            float acc = 0.f;
            #pragma unroll
            for (int i = 0; i < 16; i++) {
                float4 kv = *(float4*)&Ks[j][4 * i];
                acc += q[i].x * kv.x + q[i].y * kv.y + q[i].z * kv.z + q[i].w * kv.w;
            }
            s[j] = acc * scale;
            tmax = fmaxf(tmax, s[j]);
        }

        const float mnew = fmaxf(m, tmax);
        const float corr = __expf(m - mnew);
        float psum = 0.f;
        #pragma unroll
        for (int j = 0; j < 32; j++) {
            s[j] = __expf(s[j] - mnew);
            psum += s[j];
        }
        l = l * corr + psum;
        m = mnew;
        #pragma unroll
        for (int i = 0; i < 16; i++) {
            o[i].x *= corr; o[i].y *= corr; o[i].z *= corr; o[i].w *= corr;
        }
        #pragma unroll
        for (int j = 0; j < 32; j++) {
            const float p = s[j];
            #pragma unroll
            for (int i = 0; i < 16; i++) {
                float4 vv = *(float4*)&Vs[j][4 * i];
                o[i].x += p * vv.x; o[i].y += p * vv.y;
                o[i].z += p * vv.z; o[i].w += p * vv.w;
            }
        }
        __syncthreads();
    }

    const float invl = 1.0f / l;
    float* op = g_att + (size_t)(b * SEQ + qrow) * CC + h * DH;
    #pragma unroll
    for (int i = 0; i < 16; i++) {
        float4 ov;
        ov.x = o[i].x * invl; ov.y = o[i].y * invl;
        ov.z = o[i].z * invl; ov.w = o[i].w * invl;
        *(float4*)(op + 4 * i) = ov;
    }
}

// ---------------------------------------------------------------------------
extern "C" void kernel_launch(void* const* d_in, const int* in_sizes, int n_in,
                              void* d_out, int out_size)
{
    const float* x      = (const float*)d_in[0];
    const float* cosb   = (const float*)d_in[1];
    const float* sinb   = (const float*)d_in[2];
    const float* qkv_w  = (const float*)d_in[3];
    const float* qkv_b  = (const float*)d_in[4];
    const float* proj_w = (const float*)d_in[5];
    const float* proj_b = (const float*)d_in[6];
    const float* qn_w   = (const float*)d_in[7];
    const float* kn_w   = (const float*)d_in[8];
    float* out = (float*)d_out;

    float* qkv; cudaGetSymbolAddress((void**)&qkv, g_qkv);
    float* att; cudaGetSymbolAddress((void**)&att, g_att);

    // 1) qkv = x @ qkv_w + qkv_b      (4096 x 2304, K=768)
    {
        dim3 grid(C3 / 128, MM / 128);
        sgemm128<<<grid, 256>>>(x, qkv_w, qkv_b, qkv, MM, C3, CC);
    }
    // 2) RMSNorm + RoPE on q,k (in place)
    {
        const int rows = 2 * MM * HH;            // 98304 warps
        rmsnorm_rope<<<rows / 8, 256>>>(cosb, sinb, qn_w, kn_w);
    }
    // 3) attention
    {
        dim3 grid(Bz * HH, SEQ / 64);
        flash_attn<<<grid, 64>>>();
    }
    // 4) out = att @ proj_w + proj_b  (4096 x 768, K=768)
    {
        dim3 grid(CC / 128, MM / 128);
        sgemm128<<<grid, 256>>>(att, proj_w, proj_b, out, MM, CC, CC);
    }
}

// round 3
// speedup vs baseline: 1.2130x; 1.2130x over previous
#include <cuda_runtime.h>
#include <cuda_bf16.h>
#include <cstdint>

// Problem constants
#define Bz   2
#define SEQ  2048
#define CC   768
#define HH   12
#define DH   64
#define MM   (Bz*SEQ)        // 4096
#define C3   (3*CC)          // 2304

// Scratch (no cudaMalloc allowed)
__device__ float g_qkv[(size_t)MM * C3];   // [B*N, 3*C]
__device__ float g_att[(size_t)MM * CC];   // attention output [B*N, C]

__device__ __forceinline__ float tf32r(float x) {
    float o;
    asm("cvt.rna.tf32.f32 %0, %1;" : "=f"(o) : "f"(x));
    return o;
}

#define MMA_TF32(d, a, b)                                                     \
    asm volatile("mma.sync.aligned.m16n8k8.row.col.f32.tf32.tf32.f32 "        \
        "{%0,%1,%2,%3}, {%4,%5,%6,%7}, {%8,%9}, {%0,%1,%2,%3};"               \
        : "+f"((d)[0]), "+f"((d)[1]), "+f"((d)[2]), "+f"((d)[3])              \
        : "r"((a)[0]), "r"((a)[1]), "r"((a)[2]), "r"((a)[3]),                 \
          "r"((b)[0]), "r"((b)[1]))

// ---------------------------------------------------------------------------
// tf32 mma.sync GEMM: C = A(MxK) * Bw(KxN) + bias, row-major.
// 128x128 CTA tile, 256 threads (8 warps, 2x4), warp tile 64x32.
// K-chunks of 32, register-prefetch double-buffered smem.
// As: [128][36] floats (pad->conflict-free), Bs: [32][136].
// Requires M%128==0, N%128==0, K%32==0.
// ---------------------------------------------------------------------------
#define AS_LD   36
#define BS_LD   136
#define BUF_F   (128*AS_LD + 32*BS_LD)      // 8960 floats per buffer
#define GEMM_SMEM (2 * BUF_F * 4)           // 71680 bytes

__global__ __launch_bounds__(256) void gemm_mma(
    const float* __restrict__ A, const float* __restrict__ Bw,
    const float* __restrict__ bias, float* __restrict__ Cm,
    int Nn, int K)
{
    extern __shared__ float smem[];
    const int tid = threadIdx.x;
    const int wid = tid >> 5;
    const int lane = tid & 31;
    const int g  = lane >> 2;      // group id 0..7
    const int tg = lane & 3;       // thread-in-group 0..3
    const int wr = wid >> 2;       // 0..1  (m offset wr*64)
    const int wc = wid & 3;        // 0..3  (n offset wc*32)
    const int row0 = blockIdx.y * 128, col0 = blockIdx.x * 128;

    // gmem load mapping (4 float4 each for A and B per chunk)
    const int aRowB = tid >> 3;        // + 32*i -> 0..127
    const int aCol4 = tid & 7;
    const int bRowB = tid >> 5;        // + 8*i  -> 0..31
    const int bCol4 = tid & 31;

    float acc[4][4][4];
    #pragma unroll
    for (int mt = 0; mt < 4; mt++)
        #pragma unroll
        for (int nt = 0; nt < 4; nt++)
            #pragma unroll
            for (int r = 0; r < 4; r++) acc[mt][nt][r] = 0.f;

    const int chunks = K / 32;
    float4 ar[4], br[4];

    // prologue: load chunk 0 -> regs -> smem buf 0
    #pragma unroll
    for (int i = 0; i < 4; i++) {
        ar[i] = *(const float4*)(A + (size_t)(row0 + aRowB + 32 * i) * K + aCol4 * 4);
        br[i] = *(const float4*)(Bw + (size_t)(bRowB + 8 * i) * Nn + col0 + bCol4 * 4);
    }
    {
        float* As = smem;
        float* Bs = smem + 128 * AS_LD;
        #pragma unroll
        for (int i = 0; i < 4; i++) {
            float* ap = As + (aRowB + 32 * i) * AS_LD + aCol4 * 4;
            ap[0] = tf32r(ar[i].x); ap[1] = tf32r(ar[i].y);
            ap[2] = tf32r(ar[i].z); ap[3] = tf32r(ar[i].w);
            float* bp = Bs + (bRowB + 8 * i) * BS_LD + bCol4 * 4;
            bp[0] = tf32r(br[i].x); bp[1] = tf32r(br[i].y);
            bp[2] = tf32r(br[i].z); bp[3] = tf32r(br[i].w);
        }
    }
    __syncthreads();

    for (int c = 0; c < chunks; c++) {
        // prefetch next chunk into registers
        if (c + 1 < chunks) {
            const int k0 = (c + 1) * 32;
            #pragma unroll
            for (int i = 0; i < 4; i++) {
                ar[i] = *(const float4*)(A + (size_t)(row0 + aRowB + 32 * i) * K + k0 + aCol4 * 4);
                br[i] = *(const float4*)(Bw + (size_t)(k0 + bRowB + 8 * i) * Nn + col0 + bCol4 * 4);
            }
        }

        // compute current chunk
        const float* As = smem + (c & 1) * BUF_F;
        const float* Bs = As + 128 * AS_LD;
        #pragma unroll
        for (int kk = 0; kk < 32; kk += 8) {
            uint32_t af[4][4], bf[4][2];
            #pragma unroll
            for (int mt = 0; mt < 4; mt++) {
                const int m = wr * 64 + mt * 16 + g;
                af[mt][0] = __float_as_uint(As[m * AS_LD + kk + tg]);
                af[mt][1] = __float_as_uint(As[(m + 8) * AS_LD + kk + tg]);
                af[mt][2] = __float_as_uint(As[m * AS_LD + kk + tg + 4]);
                af[mt][3] = __float_as_uint(As[(m + 8) * AS_LD + kk + tg + 4]);
            }
            #pragma unroll
            for (int nt = 0; nt < 4; nt++) {
                const int n = wc * 32 + nt * 8 + g;
                bf[nt][0] = __float_as_uint(Bs[(kk + tg) * BS_LD + n]);
                bf[nt][1] = __float_as_uint(Bs[(kk + tg + 4) * BS_LD + n]);
            }
            #pragma unroll
            for (int mt = 0; mt < 4; mt++)
                #pragma unroll
                for (int nt = 0; nt < 4; nt++)
                    MMA_TF32(acc[mt][nt], af[mt], bf[nt]);
        }

        // store prefetched chunk into the other buffer
        if (c + 1 < chunks) {
            float* Asn = smem + ((c + 1) & 1) * BUF_F;
            float* Bsn = Asn + 128 * AS_LD;
            #pragma unroll
            for (int i = 0; i < 4; i++) {
                float* ap = Asn + (aRowB + 32 * i) * AS_LD + aCol4 * 4;
                ap[0] = tf32r(ar[i].x); ap[1] = tf32r(ar[i].y);
                ap[2] = tf32r(ar[i].z); ap[3] = tf32r(ar[i].w);
                float* bp = Bsn + (bRowB + 8 * i) * BS_LD + bCol4 * 4;
                bp[0] = tf32r(br[i].x); bp[1] = tf32r(br[i].y);
                bp[2] = tf32r(br[i].z); bp[3] = tf32r(br[i].w);
            }
        }
        __syncthreads();
    }

    // epilogue
    #pragma unroll
    for (int mt = 0; mt < 4; mt++) {
        const int r0 = row0 + wr * 64 + mt * 16 + g;
        #pragma unroll
        for (int nt = 0; nt < 4; nt++) {
            const int cc = col0 + wc * 32 + nt * 8 + 2 * tg;
            const float b0 = __ldg(bias + cc), b1 = __ldg(bias + cc + 1);
            float2 v0, v1;
            v0.x = acc[mt][nt][0] + b0; v0.y = acc[mt][nt][1] + b1;
            v1.x = acc[mt][nt][2] + b0; v1.y = acc[mt][nt][3] + b1;
            *(float2*)(Cm + (size_t)r0 * Nn + cc) = v0;
            *(float2*)(Cm + (size_t)(r0 + 8) * Nn + cc) = v1;
        }
    }
}

// ---------------------------------------------------------------------------
// Fused RMSNorm + RoPE on q and k slices of g_qkv (in place). (unchanged)
// ---------------------------------------------------------------------------
__global__ __launch_bounds__(256) void rmsnorm_rope(
    const float* __restrict__ cosb, const float* __restrict__ sinb,
    const float* __restrict__ qn_w, const float* __restrict__ kn_w)
{
    const int warp = (blockIdx.x * blockDim.x + threadIdx.x) >> 5;
    const int lane = threadIdx.x & 31;
    const int which = warp & 1;
    const int h     = (warp >> 1) % HH;
    const int bn    = warp / (2 * HH);
    const int n     = bn & (SEQ - 1);

    const float* w = which ? kn_w : qn_w;
    float* p = g_qkv + (size_t)bn * C3 + which * CC + h * DH;

    float2 v = *(float2*)(p + 2 * lane);
    float ss = v.x * v.x + v.y * v.y;
    #pragma unroll
    for (int o = 16; o; o >>= 1) ss += __shfl_xor_sync(0xffffffffu, ss, o);
    const float inv = rsqrtf(ss * (1.0f / (float)DH) + 1e-6f);

    float x0 = v.x * inv * w[2 * lane];
    float x1 = v.y * inv * w[2 * lane + 1];
    const float c = cosb[n * (DH / 2) + lane];
    const float s = sinb[n * (DH / 2) + lane];
    float2 r;
    r.x = x0 * c - x1 * s;
    r.y = x0 * s + x1 * c;
    *(float2*)(p + 2 * lane) = r;
}

// ---------------------------------------------------------------------------
// Flash attention (fp32, online softmax). (unchanged from round 1)
// ---------------------------------------------------------------------------
__global__ __launch_bounds__(64) void flash_attn()
{
    const int bh = blockIdx.x;
    const int b = bh / HH, h = bh % HH;
    const int qrow = blockIdx.y * 64 + threadIdx.x;
    const int t = threadIdx.x;

    const float* base = g_qkv + (size_t)b * SEQ * C3;
    const float* Qp = base + (size_t)qrow * C3 + h * DH;

    __shared__ float Ks[32][DH];
    __shared__ float Vs[32][DH];

    float4 q[16], o[16];
    #pragma unroll
    for (int i = 0; i < 16; i++) {
        q[i] = *(const float4*)(Qp + 4 * i);
        o[i] = make_float4(0.f, 0.f, 0.f, 0.f);
    }
    float m = -1e30f, l = 0.f;
    const float scale = 0.125f;

    for (int kt = 0; kt < SEQ; kt += 32) {
        #pragma unroll
        for (int idx = t; idx < 512; idx += 64) {
            const int rr = idx >> 4, c4 = (idx & 15) * 4;
            const float* kp = base + (size_t)(kt + rr) * C3 + CC + h * DH + c4;
            *(float4*)&Ks[rr][c4] = *(const float4*)kp;
            *(float4*)&Vs[rr][c4] = *(const float4*)(kp + CC);
        }
        __syncthreads();

        float s[32];
        float tmax = -1e30f;
        #pragma unroll
        for (int j = 0; j < 32; j++) {
            float acc2 = 0.f;
            #pragma unroll
            for (int i = 0; i < 16; i++) {
                float4 kv = *(float4*)&Ks[j][4 * i];
                acc2 += q[i].x * kv.x + q[i].y * kv.y + q[i].z * kv.z + q[i].w * kv.w;
            }
            s[j] = acc2 * scale;
            tmax = fmaxf(tmax, s[j]);
        }

        const float mnew = fmaxf(m, tmax);
        const float corr = __expf(m - mnew);
        float psum = 0.f;
        #pragma unroll
        for (int j = 0; j < 32; j++) {
            s[j] = __expf(s[j] - mnew);
            psum += s[j];
        }
        l = l * corr + psum;
        m = mnew;
        #pragma unroll
        for (int i = 0; i < 16; i++) {
            o[i].x *= corr; o[i].y *= corr; o[i].z *= corr; o[i].w *= corr;
        }
        #pragma unroll
        for (int j = 0; j < 32; j++) {
            const float p = s[j];
            #pragma unroll
            for (int i = 0; i < 16; i++) {
                float4 vv = *(float4*)&Vs[j][4 * i];
                o[i].x += p * vv.x; o[i].y += p * vv.y;
                o[i].z += p * vv.z; o[i].w += p * vv.w;
            }
        }
        __syncthreads();
    }

    const float invl = 1.0f / l;
    float* op = g_att + (size_t)(b * SEQ + qrow) * CC + h * DH;
    #pragma unroll
    for (int i = 0; i < 16; i++) {
        float4 ov;
        ov.x = o[i].x * invl; ov.y = o[i].y * invl;
        ov.z = o[i].z * invl; ov.w = o[i].w * invl;
        *(float4*)(op + 4 * i) = ov;
    }
}

// ---------------------------------------------------------------------------
extern "C" void kernel_launch(void* const* d_in, const int* in_sizes, int n_in,
                              void* d_out, int out_size)
{
    const float* x      = (const float*)d_in[0];
    const float* cosb   = (const float*)d_in[1];
    const float* sinb   = (const float*)d_in[2];
    const float* qkv_w  = (const float*)d_in[3];
    const float* qkv_b  = (const float*)d_in[4];
    const float* proj_w = (const float*)d_in[5];
    const float* proj_b = (const float*)d_in[6];
    const float* qn_w   = (const float*)d_in[7];
    const float* kn_w   = (const float*)d_in[8];
    float* out = (float*)d_out;

    float* qkv; cudaGetSymbolAddress((void**)&qkv, g_qkv);
    float* att; cudaGetSymbolAddress((void**)&att, g_att);

    static int smem_set = 0;
    if (!smem_set) {
        cudaFuncSetAttribute(gemm_mma, cudaFuncAttributeMaxDynamicSharedMemorySize,
                             GEMM_SMEM);
        smem_set = 1;
    }

    // 1) qkv = x @ qkv_w + qkv_b   (4096 x 2304, K=768) — tf32 mma.sync
    {
        dim3 grid(C3 / 128, MM / 128);
        gemm_mma<<<grid, 256, GEMM_SMEM>>>(x, qkv_w, qkv_b, qkv, C3, CC);
    }
    // 2) RMSNorm + RoPE on q,k (in place)
    {
        const int rows = 2 * MM * HH;
        rmsnorm_rope<<<rows / 8, 256>>>(cosb, sinb, qn_w, kn_w);
    }
    // 3) attention
    {
        dim3 grid(Bz * HH, SEQ / 64);
        flash_attn<<<grid, 64>>>();
    }
    // 4) out = att @ proj_w + proj_b  (4096 x 768, K=768) — tf32 mma.sync
    {
        dim3 grid(CC / 128, MM / 128);
        gemm_mma<<<grid, 256, GEMM_SMEM>>>(att, proj_w, proj_b, out, CC, CC);
    }
}

// round 4
// speedup vs baseline: 3.2876x; 2.7104x over previous
#include <cuda_runtime.h>
#include <cuda_bf16.h>
#include <cstdint>

// Problem constants
#define Bz   2
#define SEQ  2048
#define CC   768
#define HH   12
#define DH   64
#define MM   (Bz*SEQ)        // 4096
#define C3   (3*CC)          // 2304

// Scratch (no cudaMalloc allowed)
__device__ float g_qkv[(size_t)MM * C3];   // [B*N, 3*C]
__device__ float g_att[(size_t)MM * CC];   // attention output [B*N, C]

__device__ __forceinline__ float tf32r(float x) {
    float o;
    asm("cvt.rna.tf32.f32 %0, %1;" : "=f"(o) : "f"(x));
    return o;
}

#define MMA_TF32(d, a, b)                                                     \
    asm volatile("mma.sync.aligned.m16n8k8.row.col.f32.tf32.tf32.f32 "        \
        "{%0,%1,%2,%3}, {%4,%5,%6,%7}, {%8,%9}, {%0,%1,%2,%3};"               \
        : "+f"((d)[0]), "+f"((d)[1]), "+f"((d)[2]), "+f"((d)[3])              \
        : "r"((a)[0]), "r"((a)[1]), "r"((a)[2]), "r"((a)[3]),                 \
          "r"((b)[0]), "r"((b)[1]))

// ---------------------------------------------------------------------------
// tf32 mma.sync GEMM (unchanged from round 3)
// ---------------------------------------------------------------------------
#define AS_LD   36
#define BS_LD   136
#define BUF_F   (128*AS_LD + 32*BS_LD)
#define GEMM_SMEM (2 * BUF_F * 4)

__global__ __launch_bounds__(256) void gemm_mma(
    const float* __restrict__ A, const float* __restrict__ Bw,
    const float* __restrict__ bias, float* __restrict__ Cm,
    int Nn, int K)
{
    extern __shared__ float smem[];
    const int tid = threadIdx.x;
    const int wid = tid >> 5;
    const int lane = tid & 31;
    const int g  = lane >> 2;
    const int tg = lane & 3;
    const int wr = wid >> 2;
    const int wc = wid & 3;
    const int row0 = blockIdx.y * 128, col0 = blockIdx.x * 128;

    const int aRowB = tid >> 3;
    const int aCol4 = tid & 7;
    const int bRowB = tid >> 5;
    const int bCol4 = tid & 31;

    float acc[4][4][4];
    #pragma unroll
    for (int mt = 0; mt < 4; mt++)
        #pragma unroll
        for (int nt = 0; nt < 4; nt++)
            #pragma unroll
            for (int r = 0; r < 4; r++) acc[mt][nt][r] = 0.f;

    const int chunks = K / 32;
    float4 ar[4], br[4];

    #pragma unroll
    for (int i = 0; i < 4; i++) {
        ar[i] = *(const float4*)(A + (size_t)(row0 + aRowB + 32 * i) * K + aCol4 * 4);
        br[i] = *(const float4*)(Bw + (size_t)(bRowB + 8 * i) * Nn + col0 + bCol4 * 4);
    }
    {
        float* As = smem;
        float* Bs = smem + 128 * AS_LD;
        #pragma unroll
        for (int i = 0; i < 4; i++) {
            float* ap = As + (aRowB + 32 * i) * AS_LD + aCol4 * 4;
            ap[0] = tf32r(ar[i].x); ap[1] = tf32r(ar[i].y);
            ap[2] = tf32r(ar[i].z); ap[3] = tf32r(ar[i].w);
            float* bp = Bs + (bRowB + 8 * i) * BS_LD + bCol4 * 4;
            bp[0] = tf32r(br[i].x); bp[1] = tf32r(br[i].y);
            bp[2] = tf32r(br[i].z); bp[3] = tf32r(br[i].w);
        }
    }
    __syncthreads();

    for (int c = 0; c < chunks; c++) {
        if (c + 1 < chunks) {
            const int k0 = (c + 1) * 32;
            #pragma unroll
            for (int i = 0; i < 4; i++) {
                ar[i] = *(const float4*)(A + (size_t)(row0 + aRowB + 32 * i) * K + k0 + aCol4 * 4);
                br[i] = *(const float4*)(Bw + (size_t)(k0 + bRowB + 8 * i) * Nn + col0 + bCol4 * 4);
            }
        }

        const float* As = smem + (c & 1) * BUF_F;
        const float* Bs = As + 128 * AS_LD;
        #pragma unroll
        for (int kk = 0; kk < 32; kk += 8) {
            uint32_t af[4][4], bf[4][2];
            #pragma unroll
            for (int mt = 0; mt < 4; mt++) {
                const int m = wr * 64 + mt * 16 + g;
                af[mt][0] = __float_as_uint(As[m * AS_LD + kk + tg]);
                af[mt][1] = __float_as_uint(As[(m + 8) * AS_LD + kk + tg]);
                af[mt][2] = __float_as_uint(As[m * AS_LD + kk + tg + 4]);
                af[mt][3] = __float_as_uint(As[(m + 8) * AS_LD + kk + tg + 4]);
            }
            #pragma unroll
            for (int nt = 0; nt < 4; nt++) {
                const int n = wc * 32 + nt * 8 + g;
                bf[nt][0] = __float_as_uint(Bs[(kk + tg) * BS_LD + n]);
                bf[nt][1] = __float_as_uint(Bs[(kk + tg + 4) * BS_LD + n]);
            }
            #pragma unroll
            for (int mt = 0; mt < 4; mt++)
                #pragma unroll
                for (int nt = 0; nt < 4; nt++)
                    MMA_TF32(acc[mt][nt], af[mt], bf[nt]);
        }

        if (c + 1 < chunks) {
            float* Asn = smem + ((c + 1) & 1) * BUF_F;
            float* Bsn = Asn + 128 * AS_LD;
            #pragma unroll
            for (int i = 0; i < 4; i++) {
                float* ap = Asn + (aRowB + 32 * i) * AS_LD + aCol4 * 4;
                ap[0] = tf32r(ar[i].x); ap[1] = tf32r(ar[i].y);
                ap[2] = tf32r(ar[i].z); ap[3] = tf32r(ar[i].w);
                float* bp = Bsn + (bRowB + 8 * i) * BS_LD + bCol4 * 4;
                bp[0] = tf32r(br[i].x); bp[1] = tf32r(br[i].y);
                bp[2] = tf32r(br[i].z); bp[3] = tf32r(br[i].w);
            }
        }
        __syncthreads();
    }

    #pragma unroll
    for (int mt = 0; mt < 4; mt++) {
        const int r0 = row0 + wr * 64 + mt * 16 + g;
        #pragma unroll
        for (int nt = 0; nt < 4; nt++) {
            const int cc = col0 + wc * 32 + nt * 8 + 2 * tg;
            const float b0 = __ldg(bias + cc), b1 = __ldg(bias + cc + 1);
            float2 v0, v1;
            v0.x = acc[mt][nt][0] + b0; v0.y = acc[mt][nt][1] + b1;
            v1.x = acc[mt][nt][2] + b0; v1.y = acc[mt][nt][3] + b1;
            *(float2*)(Cm + (size_t)r0 * Nn + cc) = v0;
            *(float2*)(Cm + (size_t)(r0 + 8) * Nn + cc) = v1;
        }
    }
}

// ---------------------------------------------------------------------------
// Fused RMSNorm + RoPE (unchanged)
// ---------------------------------------------------------------------------
__global__ __launch_bounds__(256) void rmsnorm_rope(
    const float* __restrict__ cosb, const float* __restrict__ sinb,
    const float* __restrict__ qn_w, const float* __restrict__ kn_w)
{
    const int warp = (blockIdx.x * blockDim.x + threadIdx.x) >> 5;
    const int lane = threadIdx.x & 31;
    const int which = warp & 1;
    const int h     = (warp >> 1) % HH;
    const int bn    = warp / (2 * HH);
    const int n     = bn & (SEQ - 1);

    const float* w = which ? kn_w : qn_w;
    float* p = g_qkv + (size_t)bn * C3 + which * CC + h * DH;

    float2 v = *(float2*)(p + 2 * lane);
    float ss = v.x * v.x + v.y * v.y;
    #pragma unroll
    for (int o = 16; o; o >>= 1) ss += __shfl_xor_sync(0xffffffffu, ss, o);
    const float inv = rsqrtf(ss * (1.0f / (float)DH) + 1e-6f);

    float x0 = v.x * inv * w[2 * lane];
    float x1 = v.y * inv * w[2 * lane + 1];
    const float c = cosb[n * (DH / 2) + lane];
    const float s = sinb[n * (DH / 2) + lane];
    float2 r;
    r.x = x0 * c - x1 * s;
    r.y = x0 * s + x1 * c;
    *(float2*)(p + 2 * lane) = r;
}

// ---------------------------------------------------------------------------
// Flash attention with tf32 mma.sync.
// CTA: 256 thr (8 warps), 128 q-rows (m16/warp), K-tile = 64 keys.
// smem (floats): Ks[2][64][68] @0, Vraw[2][64][64] @8704, Vt[64][68] @16896.
// Q staged in Ks area before the pipeline starts.
// ---------------------------------------------------------------------------
#define ATT_SMEM (21248 * 4)

__global__ __launch_bounds__(256) void flash_mma()
{
    extern __shared__ float sm[];
    const int tid = threadIdx.x;
    const int lane = tid & 31, wid = tid >> 5;
    const int g = lane >> 2, tg = lane & 3;
    const int b = blockIdx.x / HH, h = blockIdx.x % HH;
    const int q0 = blockIdx.y * 128;
    const float* base = g_qkv + (size_t)b * SEQ * C3;
    const float* kvb = base + CC + h * DH;

    uint32_t smb;
    asm("{ .reg .u64 t; cvta.to.shared.u64 t, %1; cvt.u32.u64 %0, t; }"
        : "=r"(smb) : "l"(sm));

    // ---- stage Q (prescaled by Dh^-0.5, tf32), build fragments ----
    {
        const float* Qg = base + (size_t)q0 * C3 + h * DH;
        #pragma unroll
        for (int i = 0; i < 8; i++) {
            const int idx = tid + i * 256;
            const int r = idx >> 4, c = (idx & 15) * 4;
            float4 v = *(const float4*)(Qg + (size_t)r * C3 + c);
            float* d = sm + r * 68 + c;
            d[0] = tf32r(0.125f * v.x);
            d[1] = tf32r(0.125f * v.y);
            d[2] = tf32r(0.125f * v.z);
            d[3] = tf32r(0.125f * v.w);
        }
    }
    __syncthreads();
    uint32_t qf[8][4];
    {
        const float* Qs = sm + (wid * 16) * 68;
        #pragma unroll
        for (int kk = 0; kk < 8; kk++) {
            qf[kk][0] = __float_as_uint(Qs[g * 68 + kk * 8 + tg]);
            qf[kk][1] = __float_as_uint(Qs[(g + 8) * 68 + kk * 8 + tg]);
            qf[kk][2] = __float_as_uint(Qs[g * 68 + kk * 8 + tg + 4]);
            qf[kk][3] = __float_as_uint(Qs[(g + 8) * 68 + kk * 8 + tg + 4]);
        }
    }
    __syncthreads();

    // prefetch mapping: row pr (0..63), float-col pc (0/16/32/48), 4x16B each
    const int pr = tid >> 2;
    const int pc = (tid & 3) * 16;

    // prefetch tile 0
    {
        const float* src = kvb + (size_t)pr * C3 + pc;
        const uint32_t kd = smb + (uint32_t)(pr * 68 + pc) * 4u;
        const uint32_t vd = smb + (uint32_t)(8704 + pr * 64 + pc) * 4u;
        #pragma unroll
        for (int j = 0; j < 4; j++) {
            asm volatile("cp.async.cg.shared.global [%0], [%1], 16;"
                         :: "r"(kd + j * 16), "l"(src + j * 4));
            asm volatile("cp.async.cg.shared.global [%0], [%1], 16;"
                         :: "r"(vd + j * 16), "l"(src + CC + j * 4));
        }
        asm volatile("cp.async.commit_group;");
    }

    float O[8][4];
    #pragma unroll
    for (int u = 0; u < 8; u++) { O[u][0] = O[u][1] = O[u][2] = O[u][3] = 0.f; }
    float m0 = -1e30f, m1 = -1e30f, l0 = 0.f, l1 = 0.f;

    const int cvKey = tid & 63, cvQ = (tid >> 6) * 16;

    for (int it = 0; it < SEQ / 64; it++) {
        const int p = it & 1;
        asm volatile("cp.async.wait_group 0;" ::: "memory");
        __syncthreads();
        float* Kb = sm + p * 4352;
        float* Vr = sm + 8704 + p * 4096;
        float* vt = sm + 16896;
        // cvt K in place + transpose+cvt V into Vt
        #pragma unroll
        for (int j = 0; j < 4; j++) {
            float4* kp = (float4*)(Kb + cvKey * 68 + cvQ + j * 4);
            float4 kv = *kp;
            kv.x = tf32r(kv.x); kv.y = tf32r(kv.y);
            kv.z = tf32r(kv.z); kv.w = tf32r(kv.w);
            *kp = kv;
            float4 vv = *(float4*)(Vr + cvKey * 64 + cvQ + j * 4);
            const int c = cvQ + j * 4;
            vt[(c + 0) * 68 + cvKey] = tf32r(vv.x);
            vt[(c + 1) * 68 + cvKey] = tf32r(vv.y);
            vt[(c + 2) * 68 + cvKey] = tf32r(vv.z);
            vt[(c + 3) * 68 + cvKey] = tf32r(vv.w);
        }
        __syncthreads();
        if (it + 1 < SEQ / 64) {
            const float* src = kvb + (size_t)((it + 1) * 64 + pr) * C3 + pc;
            const uint32_t kd = smb + (uint32_t)((p ^ 1) * 4352 + pr * 68 + pc) * 4u;
            const uint32_t vd = smb + (uint32_t)(8704 + (p ^ 1) * 4096 + pr * 64 + pc) * 4u;
            #pragma unroll
            for (int j = 0; j < 4; j++) {
                asm volatile("cp.async.cg.shared.global [%0], [%1], 16;"
                             :: "r"(kd + j * 16), "l"(src + j * 4));
                asm volatile("cp.async.cg.shared.global [%0], [%1], 16;"
                             :: "r"(vd + j * 16), "l"(src + CC + j * 4));
            }
            asm volatile("cp.async.commit_group;");
        }

        // ---- S = Q K^T  (warp rows wid*16.., keys t*8+g) ----
        float S[8][4];
        #pragma unroll
        for (int t = 0; t < 8; t++) {
            S[t][0] = S[t][1] = S[t][2] = S[t][3] = 0.f;
            const float* kr = Kb + (t * 8 + g) * 68;
            #pragma unroll
            for (int kk = 0; kk < 8; kk++) {
                uint32_t bf[2];
                bf[0] = __float_as_uint(kr[kk * 8 + tg]);
                bf[1] = __float_as_uint(kr[kk * 8 + tg + 4]);
                MMA_TF32(S[t], qf[kk], bf);
            }
        }
        // ---- online softmax ----
        float mx0 = -1e30f, mx1 = -1e30f;
        #pragma unroll
        for (int t = 0; t < 8; t++) {
            mx0 = fmaxf(mx0, fmaxf(S[t][0], S[t][1]));
            mx1 = fmaxf(mx1, fmaxf(S[t][2], S[t][3]));
        }
        mx0 = fmaxf(mx0, __shfl_xor_sync(0xffffffffu, mx0, 1));
        mx0 = fmaxf(mx0, __shfl_xor_sync(0xffffffffu, mx0, 2));
        mx1 = fmaxf(mx1, __shfl_xor_sync(0xffffffffu, mx1, 1));
        mx1 = fmaxf(mx1, __shfl_xor_sync(0xffffffffu, mx1, 2));
        const float n0 = fmaxf(m0, mx0), n1 = fmaxf(m1, mx1);
        const float c0 = __expf(m0 - n0), c1 = __expf(m1 - n1);
        float s0 = 0.f, s1 = 0.f;
        uint32_t pf[8][4];
        #pragma unroll
        for (int t = 0; t < 8; t++) {
            const float e0 = __expf(S[t][0] - n0), e1 = __expf(S[t][1] - n0);
            const float e2 = __expf(S[t][2] - n1), e3 = __expf(S[t][3] - n1);
            s0 += e0 + e1; s1 += e2 + e3;
            pf[t][0] = __float_as_uint(tf32r(e0));
            pf[t][1] = __float_as_uint(tf32r(e1));
            pf[t][2] = __float_as_uint(tf32r(e2));
            pf[t][3] = __float_as_uint(tf32r(e3));
        }
        l0 = l0 * c0 + s0; l1 = l1 * c1 + s1;   // per-thread partial row sums
        m0 = n0; m1 = n1;
        #pragma unroll
        for (int u = 0; u < 8; u++) {
            O[u][0] *= c0; O[u][1] *= c0; O[u][2] *= c1; O[u][3] *= c1;
        }
        // ---- O += P V : route P acc-layout -> A-operand layout via shfl ----
        const int sA = (lane & ~3) | (tg >> 1);
        const bool odd = (tg & 1);
        #pragma unroll
        for (int t = 0; t < 8; t++) {
            const uint32_t x0 = __shfl_sync(0xffffffffu, pf[t][0], sA);
            const uint32_t x1 = __shfl_sync(0xffffffffu, pf[t][1], sA);
            const uint32_t x2 = __shfl_sync(0xffffffffu, pf[t][2], sA);
            const uint32_t x3 = __shfl_sync(0xffffffffu, pf[t][3], sA);
            const uint32_t y0 = __shfl_sync(0xffffffffu, pf[t][0], sA + 2);
            const uint32_t y1 = __shfl_sync(0xffffffffu, pf[t][1], sA + 2);
            const uint32_t y2 = __shfl_sync(0xffffffffu, pf[t][2], sA + 2);
            const uint32_t y3 = __shfl_sync(0xffffffffu, pf[t][3], sA + 2);
            uint32_t af[4];
            af[0] = odd ? x1 : x0;   // P[g   ][8t+tg]
            af[1] = odd ? x3 : x2;   // P[g+8 ][8t+tg]
            af[2] = odd ? y1 : y0;   // P[g   ][8t+tg+4]
            af[3] = odd ? y3 : y2;   // P[g+8 ][8t+tg+4]
            #pragma unroll
            for (int u = 0; u < 8; u++) {
                uint32_t bf[2];
                bf[0] = __float_as_uint(vt[(u * 8 + g) * 68 + t * 8 + tg]);
                bf[1] = __float_as_uint(vt[(u * 8 + g) * 68 + t * 8 + tg + 4]);
                MMA_TF32(O[u], af, bf);
            }
        }
    }

    // epilogue: finish row-sum reduction, normalize, store
    l0 += __shfl_xor_sync(0xffffffffu, l0, 1);
    l0 += __shfl_xor_sync(0xffffffffu, l0, 2);
    l1 += __shfl_xor_sync(0xffffffffu, l1, 1);
    l1 += __shfl_xor_sync(0xffffffffu, l1, 2);
    const float i0 = 1.f / l0, i1 = 1.f / l1;
    const int r0 = q0 + wid * 16 + g;
    float* o0 = g_att + (size_t)(b * SEQ + r0) * CC + h * DH;
    float* o1 = o0 + (size_t)8 * CC;
    #pragma unroll
    for (int u = 0; u < 8; u++) {
        float2 v0, v1;
        v0.x = O[u][0] * i0; v0.y = O[u][1] * i0;
        v1.x = O[u][2] * i1; v1.y = O[u][3] * i1;
        *(float2*)(o0 + u * 8 + 2 * tg) = v0;
        *(float2*)(o1 + u * 8 + 2 * tg) = v1;
    }
}

// ---------------------------------------------------------------------------
extern "C" void kernel_launch(void* const* d_in, const int* in_sizes, int n_in,
                              void* d_out, int out_size)
{
    const float* x      = (const float*)d_in[0];
    const float* cosb   = (const float*)d_in[1];
    const float* sinb   = (const float*)d_in[2];
    const float* qkv_w  = (const float*)d_in[3];
    const float* qkv_b  = (const float*)d_in[4];
    const float* proj_w = (const float*)d_in[5];
    const float* proj_b = (const float*)d_in[6];
    const float* qn_w   = (const float*)d_in[7];
    const float* kn_w   = (const float*)d_in[8];
    float* out = (float*)d_out;

    float* qkv; cudaGetSymbolAddress((void**)&qkv, g_qkv);
    float* att; cudaGetSymbolAddress((void**)&att, g_att);

    static int smem_set = 0;
    if (!smem_set) {
        cudaFuncSetAttribute(gemm_mma, cudaFuncAttributeMaxDynamicSharedMemorySize,
                             GEMM_SMEM);
        cudaFuncSetAttribute(flash_mma, cudaFuncAttributeMaxDynamicSharedMemorySize,
                             ATT_SMEM);
        smem_set = 1;
    }

    // 1) qkv = x @ qkv_w + qkv_b
    {
        dim3 grid(C3 / 128, MM / 128);
        gemm_mma<<<grid, 256, GEMM_SMEM>>>(x, qkv_w, qkv_b, qkv, C3, CC);
    }
    // 2) RMSNorm + RoPE on q,k (in place)
    {
        const int rows = 2 * MM * HH;
        rmsnorm_rope<<<rows / 8, 256>>>(cosb, sinb, qn_w, kn_w);
    }
    // 3) attention — tf32 mma.sync flash
    {
        dim3 grid(Bz * HH, SEQ / 128);
        flash_mma<<<grid, 256, ATT_SMEM>>>();
    }
    // 4) out = att @ proj_w + proj_b
    {
        dim3 grid(CC / 128, MM / 128);
        gemm_mma<<<grid, 256, GEMM_SMEM>>>(att, proj_w, proj_b, out, CC, CC);
    }
}

// round 5
// speedup vs baseline: 3.7606x; 1.1438x over previous
#include <cuda_runtime.h>
#include <cuda_bf16.h>
#include <cstdint>

// Problem constants
#define Bz   2
#define SEQ  2048
#define CC   768
#define HH   12
#define DH   64
#define MM   (Bz*SEQ)        // 4096
#define C3   (3*CC)          // 2304

// Scratch (no cudaMalloc allowed)
__device__ float g_qkv[(size_t)MM * C3];   // [B*N, 3*C]
__device__ float g_att[(size_t)MM * CC];   // attention output [B*N, C]

__device__ __forceinline__ float tf32r(float x) {
    float o;
    asm("cvt.rna.tf32.f32 %0, %1;" : "=f"(o) : "f"(x));
    return o;
}
__device__ __forceinline__ uint32_t tf32u(float x) {
    float o;
    asm("cvt.rna.tf32.f32 %0, %1;" : "=f"(o) : "f"(x));
    return __float_as_uint(o);
}

#define MMA_TF32(d, a, b)                                                     \
    asm volatile("mma.sync.aligned.m16n8k8.row.col.f32.tf32.tf32.f32 "        \
        "{%0,%1,%2,%3}, {%4,%5,%6,%7}, {%8,%9}, {%0,%1,%2,%3};"               \
        : "+f"((d)[0]), "+f"((d)[1]), "+f"((d)[2]), "+f"((d)[3])              \
        : "r"((a)[0]), "r"((a)[1]), "r"((a)[2]), "r"((a)[3]),                 \
          "r"((b)[0]), "r"((b)[1]))

// ---------------------------------------------------------------------------
// tf32 mma.sync GEMM, cp.async 2-stage, 2 CTAs/SM.
// 128x128 CTA tile, 256 threads (8 warps, 2x4), warp tile 64x32.
// As: [128][36], Bs: [32][136]. tf32 cvt at fragment load.
// ---------------------------------------------------------------------------
#define AS_LD   36
#define BS_LD   136
#define BUF_F   (128*AS_LD + 32*BS_LD)      // 8960 floats
#define GEMM_SMEM (2 * BUF_F * 4)           // 71680 bytes

__global__ __launch_bounds__(256, 2) void gemm_mma(
    const float* __restrict__ A, const float* __restrict__ Bw,
    const float* __restrict__ bias, float* __restrict__ Cm,
    int Nn, int K)
{
    extern __shared__ float smem[];
    uint32_t smb;
    asm("{ .reg .u64 t; cvta.to.shared.u64 t, %1; cvt.u32.u64 %0, t; }"
        : "=r"(smb) : "l"(smem));
    const int tid = threadIdx.x;
    const int wid = tid >> 5;
    const int lane = tid & 31;
    const int g  = lane >> 2;
    const int tg = lane & 3;
    const int wr = wid >> 2;
    const int wc = wid & 3;
    const int row0 = blockIdx.y * 128, col0 = blockIdx.x * 128;

    const int aRowB = tid >> 3;
    const int aCol4 = tid & 7;
    const int bRowB = tid >> 5;
    const int bCol4 = tid & 31;

    float acc[4][4][4];
    #pragma unroll
    for (int mt = 0; mt < 4; mt++)
        #pragma unroll
        for (int nt = 0; nt < 4; nt++)
            #pragma unroll
            for (int r = 0; r < 4; r++) acc[mt][nt][r] = 0.f;

    const int chunks = K / 32;

#define GISSUE(cc, pp) do {                                                   \
    const int k0_ = (cc) * 32;                                                \
    _Pragma("unroll")                                                         \
    for (int i_ = 0; i_ < 4; i_++) {                                          \
        const float* as_ = A + (size_t)(row0 + aRowB + 32 * i_) * K + k0_ + aCol4 * 4; \
        const uint32_t ad_ = smb + (uint32_t)((pp) * BUF_F + (aRowB + 32 * i_) * AS_LD + aCol4 * 4) * 4u; \
        asm volatile("cp.async.cg.shared.global [%0], [%1], 16;" :: "r"(ad_), "l"(as_)); \
        const float* bs_ = Bw + (size_t)(k0_ + bRowB + 8 * i_) * Nn + col0 + bCol4 * 4; \
        const uint32_t bd_ = smb + (uint32_t)((pp) * BUF_F + 128 * AS_LD + (bRowB + 8 * i_) * BS_LD + bCol4 * 4) * 4u; \
        asm volatile("cp.async.cg.shared.global [%0], [%1], 16;" :: "r"(bd_), "l"(bs_)); \
    }                                                                         \
    asm volatile("cp.async.commit_group;");                                   \
} while (0)

    GISSUE(0, 0);

    for (int c = 0; c < chunks; c++) {
        __syncthreads();   // all warps done reading buffer (c+1)&1
        if (c + 1 < chunks) {
            GISSUE(c + 1, (c + 1) & 1);
            asm volatile("cp.async.wait_group 1;" ::: "memory");
        } else {
            asm volatile("cp.async.wait_group 0;" ::: "memory");
        }
        __syncthreads();   // chunk c data visible to all warps

        const float* As = smem + (c & 1) * BUF_F;
        const float* Bs = As + 128 * AS_LD;
        #pragma unroll
        for (int kk = 0; kk < 32; kk += 8) {
            uint32_t af[4][4], bf[4][2];
            #pragma unroll
            for (int mt = 0; mt < 4; mt++) {
                const int m = wr * 64 + mt * 16 + g;
                af[mt][0] = tf32u(As[m * AS_LD + kk + tg]);
                af[mt][1] = tf32u(As[(m + 8) * AS_LD + kk + tg]);
                af[mt][2] = tf32u(As[m * AS_LD + kk + tg + 4]);
                af[mt][3] = tf32u(As[(m + 8) * AS_LD + kk + tg + 4]);
            }
            #pragma unroll
            for (int nt = 0; nt < 4; nt++) {
                const int n = wc * 32 + nt * 8 + g;
                bf[nt][0] = tf32u(Bs[(kk + tg) * BS_LD + n]);
                bf[nt][1] = tf32u(Bs[(kk + tg + 4) * BS_LD + n]);
            }
            #pragma unroll
            for (int mt = 0; mt < 4; mt++)
                #pragma unroll
                for (int nt = 0; nt < 4; nt++)
                    MMA_TF32(acc[mt][nt], af[mt], bf[nt]);
        }
    }

    #pragma unroll
    for (int mt = 0; mt < 4; mt++) {
        const int r0 = row0 + wr * 64 + mt * 16 + g;
        #pragma unroll
        for (int nt = 0; nt < 4; nt++) {
            const int cc = col0 + wc * 32 + nt * 8 + 2 * tg;
            const float b0 = __ldg(bias + cc), b1 = __ldg(bias + cc + 1);
            float2 v0, v1;
            v0.x = acc[mt][nt][0] + b0; v0.y = acc[mt][nt][1] + b1;
            v1.x = acc[mt][nt][2] + b0; v1.y = acc[mt][nt][3] + b1;
            *(float2*)(Cm + (size_t)r0 * Nn + cc) = v0;
            *(float2*)(Cm + (size_t)(r0 + 8) * Nn + cc) = v1;
        }
    }
}

// ---------------------------------------------------------------------------
// Fused RMSNorm + RoPE (unchanged)
// ---------------------------------------------------------------------------
__global__ __launch_bounds__(256) void rmsnorm_rope(
    const float* __restrict__ cosb, const float* __restrict__ sinb,
    const float* __restrict__ qn_w, const float* __restrict__ kn_w)
{
    const int warp = (blockIdx.x * blockDim.x + threadIdx.x) >> 5;
    const int lane = threadIdx.x & 31;
    const int which = warp & 1;
    const int h     = (warp >> 1) % HH;
    const int bn    = warp / (2 * HH);
    const int n     = bn & (SEQ - 1);

    const float* w = which ? kn_w : qn_w;
    float* p = g_qkv + (size_t)bn * C3 + which * CC + h * DH;

    float2 v = *(float2*)(p + 2 * lane);
    float ss = v.x * v.x + v.y * v.y;
    #pragma unroll
    for (int o = 16; o; o >>= 1) ss += __shfl_xor_sync(0xffffffffu, ss, o);
    const float inv = rsqrtf(ss * (1.0f / (float)DH) + 1e-6f);

    float x0 = v.x * inv * w[2 * lane];
    float x1 = v.y * inv * w[2 * lane + 1];
    const float c = cosb[n * (DH / 2) + lane];
    const float s = sinb[n * (DH / 2) + lane];
    float2 r;
    r.x = x0 * c - x1 * s;
    r.y = x0 * s + x1 * c;
    *(float2*)(p + 2 * lane) = r;
}

// ---------------------------------------------------------------------------
// Flash attention, tf32 mma.sync, 2 CTAs/SM, exp2-domain softmax.
// smem (floats): Ks[2][64][68] @0, Vraw[2][64][64] @8704, Vt[64][68] @16896.
// ---------------------------------------------------------------------------
#define ATT_SMEM (21248 * 4)
#define QSCALE   (0.125f * 1.44269504f)    // Dh^-0.5 * log2(e)

__global__ __launch_bounds__(256, 2) void flash_mma()
{
    extern __shared__ float sm[];
    const int tid = threadIdx.x;
    const int lane = tid & 31, wid = tid >> 5;
    const int g = lane >> 2, tg = lane & 3;
    const int b = blockIdx.x / HH, h = blockIdx.x % HH;
    const int q0 = blockIdx.y * 128;
    const float* base = g_qkv + (size_t)b * SEQ * C3;
    const float* kvb = base + CC + h * DH;

    uint32_t smb;
    asm("{ .reg .u64 t; cvta.to.shared.u64 t, %1; cvt.u32.u64 %0, t; }"
        : "=r"(smb) : "l"(sm));

    // ---- stage Q (prescaled by Dh^-0.5 * log2e, tf32), build fragments ----
    {
        const float* Qg = base + (size_t)q0 * C3 + h * DH;
        #pragma unroll
        for (int i = 0; i < 8; i++) {
            const int idx = tid + i * 256;
            const int r = idx >> 4, c = (idx & 15) * 4;
            float4 v = *(const float4*)(Qg + (size_t)r * C3 + c);
            float* d = sm + r * 68 + c;
            d[0] = tf32r(QSCALE * v.x);
            d[1] = tf32r(QSCALE * v.y);
            d[2] = tf32r(QSCALE * v.z);
            d[3] = tf32r(QSCALE * v.w);
        }
    }
    __syncthreads();
    uint32_t qf[8][4];
    {
        const float* Qs = sm + (wid * 16) * 68;
        #pragma unroll
        for (int kk = 0; kk < 8; kk++) {
            qf[kk][0] = __float_as_uint(Qs[g * 68 + kk * 8 + tg]);
            qf[kk][1] = __float_as_uint(Qs[(g + 8) * 68 + kk * 8 + tg]);
            qf[kk][2] = __float_as_uint(Qs[g * 68 + kk * 8 + tg + 4]);
            qf[kk][3] = __float_as_uint(Qs[(g + 8) * 68 + kk * 8 + tg + 4]);
        }
    }
    __syncthreads();

    const int pr = tid >> 2;
    const int pc = (tid & 3) * 16;

    // prefetch tile 0
    {
        const float* src = kvb + (size_t)pr * C3 + pc;
        const uint32_t kd = smb + (uint32_t)(pr * 68 + pc) * 4u;
        const uint32_t vd = smb + (uint32_t)(8704 + pr * 64 + pc) * 4u;
        #pragma unroll
        for (int j = 0; j < 4; j++) {
            asm volatile("cp.async.cg.shared.global [%0], [%1], 16;"
                         :: "r"(kd + j * 16), "l"(src + j * 4));
            asm volatile("cp.async.cg.shared.global [%0], [%1], 16;"
                         :: "r"(vd + j * 16), "l"(src + CC + j * 4));
        }
        asm volatile("cp.async.commit_group;");
    }

    float O[8][4];
    #pragma unroll
    for (int u = 0; u < 8; u++) { O[u][0] = O[u][1] = O[u][2] = O[u][3] = 0.f; }
    float m0 = -1e30f, m1 = -1e30f, l0 = 0.f, l1 = 0.f;

    const int cvKey = tid & 63, cvQ = (tid >> 6) * 16;
    const int sA = (lane & ~3) | (tg >> 1);
    const bool odd = (tg & 1);

    for (int it = 0; it < SEQ / 64; it++) {
        const int p = it & 1;
        asm volatile("cp.async.wait_group 0;" ::: "memory");
        __syncthreads();
        float* Kb = sm + p * 4352;
        float* Vr = sm + 8704 + p * 4096;
        float* vt = sm + 16896;
        // cvt K in place + transpose+cvt V into Vt
        #pragma unroll
        for (int j = 0; j < 4; j++) {
            float4* kp = (float4*)(Kb + cvKey * 68 + cvQ + j * 4);
            float4 kv = *kp;
            kv.x = tf32r(kv.x); kv.y = tf32r(kv.y);
            kv.z = tf32r(kv.z); kv.w = tf32r(kv.w);
            *kp = kv;
            float4 vv = *(float4*)(Vr + cvKey * 64 + cvQ + j * 4);
            const int c = cvQ + j * 4;
            vt[(c + 0) * 68 + cvKey] = tf32r(vv.x);
            vt[(c + 1) * 68 + cvKey] = tf32r(vv.y);
            vt[(c + 2) * 68 + cvKey] = tf32r(vv.z);
            vt[(c + 3) * 68 + cvKey] = tf32r(vv.w);
        }
        __syncthreads();
        if (it + 1 < SEQ / 64) {
            const float* src = kvb + (size_t)((it + 1) * 64 + pr) * C3 + pc;
            const uint32_t kd = smb + (uint32_t)((p ^ 1) * 4352 + pr * 68 + pc) * 4u;
            const uint32_t vd = smb + (uint32_t)(8704 + (p ^ 1) * 4096 + pr * 64 + pc) * 4u;
            #pragma unroll
            for (int j = 0; j < 4; j++) {
                asm volatile("cp.async.cg.shared.global [%0], [%1], 16;"
                             :: "r"(kd + j * 16), "l"(src + j * 4));
                asm volatile("cp.async.cg.shared.global [%0], [%1], 16;"
                             :: "r"(vd + j * 16), "l"(src + CC + j * 4));
            }
            asm volatile("cp.async.commit_group;");
        }

        // ---- S = Q K^T  (logits already in log2 domain via Q prescale) ----
        float S[8][4];
        #pragma unroll
        for (int t = 0; t < 8; t++) {
            S[t][0] = S[t][1] = S[t][2] = S[t][3] = 0.f;
            const float* kr = Kb + (t * 8 + g) * 68;
            #pragma unroll
            for (int kk = 0; kk < 8; kk++) {
                uint32_t bf[2];
                bf[0] = __float_as_uint(kr[kk * 8 + tg]);
                bf[1] = __float_as_uint(kr[kk * 8 + tg + 4]);
                MMA_TF32(S[t], qf[kk], bf);
            }
        }
        // ---- online softmax (base-2) ----
        float mx0 = -1e30f, mx1 = -1e30f;
        #pragma unroll
        for (int t = 0; t < 8; t++) {
            mx0 = fmaxf(mx0, fmaxf(S[t][0], S[t][1]));
            mx1 = fmaxf(mx1, fmaxf(S[t][2], S[t][3]));
        }
        mx0 = fmaxf(mx0, __shfl_xor_sync(0xffffffffu, mx0, 1));
        mx0 = fmaxf(mx0, __shfl_xor_sync(0xffffffffu, mx0, 2));
        mx1 = fmaxf(mx1, __shfl_xor_sync(0xffffffffu, mx1, 1));
        mx1 = fmaxf(mx1, __shfl_xor_sync(0xffffffffu, mx1, 2));
        const float n0 = fmaxf(m0, mx0), n1 = fmaxf(m1, mx1);
        const float c0 = exp2f(m0 - n0), c1 = exp2f(m1 - n1);
        m0 = n0; m1 = n1;
        #pragma unroll
        for (int u = 0; u < 8; u++) {
            O[u][0] *= c0; O[u][1] *= c0; O[u][2] *= c1; O[u][3] *= c1;
        }
        float s0 = 0.f, s1 = 0.f;
        // ---- per 8-key group: exp -> shuffle-route -> MMA into O ----
        #pragma unroll
        for (int t = 0; t < 8; t++) {
            const float e0 = exp2f(S[t][0] - n0), e1 = exp2f(S[t][1] - n0);
            const float e2 = exp2f(S[t][2] - n1), e3 = exp2f(S[t][3] - n1);
            s0 += e0 + e1; s1 += e2 + e3;
            const uint32_t p0 = tf32u(e0), p1 = tf32u(e1);
            const uint32_t p2 = tf32u(e2), p3 = tf32u(e3);
            const uint32_t x0 = __shfl_sync(0xffffffffu, p0, sA);
            const uint32_t x1 = __shfl_sync(0xffffffffu, p1, sA);
            const uint32_t x2 = __shfl_sync(0xffffffffu, p2, sA);
            const uint32_t x3 = __shfl_sync(0xffffffffu, p3, sA);
            const uint32_t y0 = __shfl_sync(0xffffffffu, p0, sA + 2);
            const uint32_t y1 = __shfl_sync(0xffffffffu, p1, sA + 2);
            const uint32_t y2 = __shfl_sync(0xffffffffu, p2, sA + 2);
            const uint32_t y3 = __shfl_sync(0xffffffffu, p3, sA + 2);
            uint32_t af[4];
            af[0] = odd ? x1 : x0;
            af[1] = odd ? x3 : x2;
            af[2] = odd ? y1 : y0;
            af[3] = odd ? y3 : y2;
            #pragma unroll
            for (int u = 0; u < 8; u++) {
                uint32_t bf[2];
                bf[0] = __float_as_uint(vt[(u * 8 + g) * 68 + t * 8 + tg]);
                bf[1] = __float_as_uint(vt[(u * 8 + g) * 68 + t * 8 + tg + 4]);
                MMA_TF32(O[u], af, bf);
            }
        }
        l0 = l0 * c0 + s0; l1 = l1 * c1 + s1;
    }

    // epilogue
    l0 += __shfl_xor_sync(0xffffffffu, l0, 1);
    l0 += __shfl_xor_sync(0xffffffffu, l0, 2);
    l1 += __shfl_xor_sync(0xffffffffu, l1, 1);
    l1 += __shfl_xor_sync(0xffffffffu, l1, 2);
    const float i0 = 1.f / l0, i1 = 1.f / l1;
    const int r0 = q0 + wid * 16 + g;
    float* o0 = g_att + (size_t)(b * SEQ + r0) * CC + h * DH;
    float* o1 = o0 + (size_t)8 * CC;
    #pragma unroll
    for (int u = 0; u < 8; u++) {
        float2 v0, v1;
        v0.x = O[u][0] * i0; v0.y = O[u][1] * i0;
        v1.x = O[u][2] * i1; v1.y = O[u][3] * i1;
        *(float2*)(o0 + u * 8 + 2 * tg) = v0;
        *(float2*)(o1 + u * 8 + 2 * tg) = v1;
    }
}

// ---------------------------------------------------------------------------
extern "C" void kernel_launch(void* const* d_in, const int* in_sizes, int n_in,
                              void* d_out, int out_size)
{
    const float* x      = (const float*)d_in[0];
    const float* cosb   = (const float*)d_in[1];
    const float* sinb   = (const float*)d_in[2];
    const float* qkv_w  = (const float*)d_in[3];
    const float* qkv_b  = (const float*)d_in[4];
    const float* proj_w = (const float*)d_in[5];
    const float* proj_b = (const float*)d_in[6];
    const float* qn_w   = (const float*)d_in[7];
    const float* kn_w   = (const float*)d_in[8];
    float* out = (float*)d_out;

    float* qkv; cudaGetSymbolAddress((void**)&qkv, g_qkv);
    float* att; cudaGetSymbolAddress((void**)&att, g_att);

    static int smem_set = 0;
    if (!smem_set) {
        cudaFuncSetAttribute(gemm_mma, cudaFuncAttributeMaxDynamicSharedMemorySize,
                             GEMM_SMEM);
        cudaFuncSetAttribute(flash_mma, cudaFuncAttributeMaxDynamicSharedMemorySize,
                             ATT_SMEM);
        smem_set = 1;
    }

    // 1) qkv = x @ qkv_w + qkv_b
    {
        dim3 grid(C3 / 128, MM / 128);
        gemm_mma<<<grid, 256, GEMM_SMEM>>>(x, qkv_w, qkv_b, qkv, C3, CC);
    }
    // 2) RMSNorm + RoPE on q,k (in place)
    {
        const int rows = 2 * MM * HH;
        rmsnorm_rope<<<rows / 8, 256>>>(cosb, sinb, qn_w, kn_w);
    }
    // 3) attention — tf32 mma.sync flash
    {
        dim3 grid(Bz * HH, SEQ / 128);
        flash_mma<<<grid, 256, ATT_SMEM>>>();
    }
    // 4) out = att @ proj_w + proj_b
    {
        dim3 grid(CC / 128, MM / 128);
        gemm_mma<<<grid, 256, GEMM_SMEM>>>(att, proj_w, proj_b, out, CC, CC);
    }
}

// round 6
// speedup vs baseline: 3.8798x; 1.0317x over previous
#include <cuda_runtime.h>
#include <cuda_bf16.h>
#include <cstdint>

// Problem constants
#define Bz   2
#define SEQ  2048
#define CC   768
#define HH   12
#define DH   64
#define MM   (Bz*SEQ)        // 4096
#define C3   (3*CC)          // 2304

// Scratch (no cudaMalloc allowed)
__device__ float g_qkv[(size_t)MM * C3];   // [B*N, 3*C]
__device__ float g_att[(size_t)MM * CC];   // attention output [B*N, C]

__device__ __forceinline__ float tf32r(float x) {
    float o;
    asm("cvt.rna.tf32.f32 %0, %1;" : "=f"(o) : "f"(x));
    return o;
}
__device__ __forceinline__ uint32_t tf32u(float x) {
    float o;
    asm("cvt.rna.tf32.f32 %0, %1;" : "=f"(o) : "f"(x));
    return __float_as_uint(o);
}

#define MMA_TF32(d, a, b)                                                     \
    asm volatile("mma.sync.aligned.m16n8k8.row.col.f32.tf32.tf32.f32 "        \
        "{%0,%1,%2,%3}, {%4,%5,%6,%7}, {%8,%9}, {%0,%1,%2,%3};"               \
        : "+f"((d)[0]), "+f"((d)[1]), "+f"((d)[2]), "+f"((d)[3])              \
        : "r"((a)[0]), "r"((a)[1]), "r"((a)[2]), "r"((a)[3]),                 \
          "r"((b)[0]), "r"((b)[1]))

// ---------------------------------------------------------------------------
// tf32 mma.sync GEMM, cp.async 3-stage, 2 CTAs/SM, one sync per chunk.
// 128x128 CTA tile, 256 threads (8 warps, 2x4), warp tile 64x32.
// As: [128][36], Bs: [32][136]. tf32 cvt at fragment load.
// ---------------------------------------------------------------------------
#define AS_LD   36
#define BS_LD   136
#define BUF_F   (128*AS_LD + 32*BS_LD)      // 8960 floats
#define GEMM_SMEM (3 * BUF_F * 4)           // 107520 bytes

__global__ __launch_bounds__(256, 2) void gemm_mma(
    const float* __restrict__ A, const float* __restrict__ Bw,
    const float* __restrict__ bias, float* __restrict__ Cm,
    int Nn, int K)
{
    extern __shared__ float smem[];
    uint32_t smb;
    asm("{ .reg .u64 t; cvta.to.shared.u64 t, %1; cvt.u32.u64 %0, t; }"
        : "=r"(smb) : "l"(smem));
    const int tid = threadIdx.x;
    const int wid = tid >> 5;
    const int lane = tid & 31;
    const int g  = lane >> 2;
    const int tg = lane & 3;
    const int wr = wid >> 2;
    const int wc = wid & 3;
    const int row0 = blockIdx.y * 128, col0 = blockIdx.x * 128;

    const int aRowB = tid >> 3;
    const int aCol4 = tid & 7;
    const int bRowB = tid >> 5;
    const int bCol4 = tid & 31;

    float acc[4][4][4];
    #pragma unroll
    for (int mt = 0; mt < 4; mt++)
        #pragma unroll
        for (int nt = 0; nt < 4; nt++)
            #pragma unroll
            for (int r = 0; r < 4; r++) acc[mt][nt][r] = 0.f;

    const int chunks = K / 32;   // >= 2 for all uses here

#define GISSUE(cc, pp) do {                                                   \
    const int k0_ = (cc) * 32;                                                \
    _Pragma("unroll")                                                         \
    for (int i_ = 0; i_ < 4; i_++) {                                          \
        const float* as_ = A + (size_t)(row0 + aRowB + 32 * i_) * K + k0_ + aCol4 * 4; \
        const uint32_t ad_ = smb + (uint32_t)((pp) * BUF_F + (aRowB + 32 * i_) * AS_LD + aCol4 * 4) * 4u; \
        asm volatile("cp.async.cg.shared.global [%0], [%1], 16;" :: "r"(ad_), "l"(as_)); \
        const float* bs_ = Bw + (size_t)(k0_ + bRowB + 8 * i_) * Nn + col0 + bCol4 * 4; \
        const uint32_t bd_ = smb + (uint32_t)((pp) * BUF_F + 128 * AS_LD + (bRowB + 8 * i_) * BS_LD + bCol4 * 4) * 4u; \
        asm volatile("cp.async.cg.shared.global [%0], [%1], 16;" :: "r"(bd_), "l"(bs_)); \
    }                                                                         \
    asm volatile("cp.async.commit_group;");                                   \
} while (0)

    GISSUE(0, 0);
    GISSUE(1, 1);

    for (int c = 0; c < chunks; c++) {
        if (c + 1 < chunks) {
            asm volatile("cp.async.wait_group 1;" ::: "memory");
        } else {
            asm volatile("cp.async.wait_group 0;" ::: "memory");
        }
        __syncthreads();
        if (c + 2 < chunks) GISSUE(c + 2, (c + 2) % 3);

        const float* As = smem + (c % 3) * BUF_F;
        const float* Bs = As + 128 * AS_LD;
        #pragma unroll
        for (int kk = 0; kk < 32; kk += 8) {
            uint32_t af[4][4], bf[4][2];
            #pragma unroll
            for (int mt = 0; mt < 4; mt++) {
                const int m = wr * 64 + mt * 16 + g;
                af[mt][0] = tf32u(As[m * AS_LD + kk + tg]);
                af[mt][1] = tf32u(As[(m + 8) * AS_LD + kk + tg]);
                af[mt][2] = tf32u(As[m * AS_LD + kk + tg + 4]);
                af[mt][3] = tf32u(As[(m + 8) * AS_LD + kk + tg + 4]);
            }
            #pragma unroll
            for (int nt = 0; nt < 4; nt++) {
                const int n = wc * 32 + nt * 8 + g;
                bf[nt][0] = tf32u(Bs[(kk + tg) * BS_LD + n]);
                bf[nt][1] = tf32u(Bs[(kk + tg + 4) * BS_LD + n]);
            }
            #pragma unroll
            for (int mt = 0; mt < 4; mt++)
                #pragma unroll
                for (int nt = 0; nt < 4; nt++)
                    MMA_TF32(acc[mt][nt], af[mt], bf[nt]);
        }
    }

    #pragma unroll
    for (int mt = 0; mt < 4; mt++) {
        const int r0 = row0 + wr * 64 + mt * 16 + g;
        #pragma unroll
        for (int nt = 0; nt < 4; nt++) {
            const int cc = col0 + wc * 32 + nt * 8 + 2 * tg;
            const float b0 = __ldg(bias + cc), b1 = __ldg(bias + cc + 1);
            float2 v0, v1;
            v0.x = acc[mt][nt][0] + b0; v0.y = acc[mt][nt][1] + b1;
            v1.x = acc[mt][nt][2] + b0; v1.y = acc[mt][nt][3] + b1;
            *(float2*)(Cm + (size_t)r0 * Nn + cc) = v0;
            *(float2*)(Cm + (size_t)(r0 + 8) * Nn + cc) = v1;
        }
    }
}

// ---------------------------------------------------------------------------
// Fused RMSNorm + RoPE (unchanged)
// ---------------------------------------------------------------------------
__global__ __launch_bounds__(256) void rmsnorm_rope(
    const float* __restrict__ cosb, const float* __restrict__ sinb,
    const float* __restrict__ qn_w, const float* __restrict__ kn_w)
{
    const int warp = (blockIdx.x * blockDim.x + threadIdx.x) >> 5;
    const int lane = threadIdx.x & 31;
    const int which = warp & 1;
    const int h     = (warp >> 1) % HH;
    const int bn    = warp / (2 * HH);
    const int n     = bn & (SEQ - 1);

    const float* w = which ? kn_w : qn_w;
    float* p = g_qkv + (size_t)bn * C3 + which * CC + h * DH;

    float2 v = *(float2*)(p + 2 * lane);
    float ss = v.x * v.x + v.y * v.y;
    #pragma unroll
    for (int o = 16; o; o >>= 1) ss += __shfl_xor_sync(0xffffffffu, ss, o);
    const float inv = rsqrtf(ss * (1.0f / (float)DH) + 1e-6f);

    float x0 = v.x * inv * w[2 * lane];
    float x1 = v.y * inv * w[2 * lane + 1];
    const float c = cosb[n * (DH / 2) + lane];
    const float s = sinb[n * (DH / 2) + lane];
    float2 r;
    r.x = x0 * c - x1 * s;
    r.y = x0 * s + x1 * c;
    *(float2*)(p + 2 * lane) = r;
}

// ---------------------------------------------------------------------------
// Flash attention, tf32 mma.sync, 2 CTAs/SM, exp2 softmax.
// NO transpose/cvt pass: V read row-major as B operand; tf32 cvt at frag load.
// smem floats: Ks[2][64][68] @0 (4352/buf), Vs[2][64][72] @8704 (4608/buf).
// Q staged in Ks area (128x68) before the pipeline starts.
// ---------------------------------------------------------------------------
#define KS_LD 68
#define VS_LD 72
#define ATT_SMEM (17920 * 4)              // 71680 bytes
#define QSCALE   (0.125f * 1.44269504f)   // Dh^-0.5 * log2(e)

__global__ __launch_bounds__(256, 2) void flash_mma()
{
    extern __shared__ float sm[];
    const int tid = threadIdx.x;
    const int lane = tid & 31, wid = tid >> 5;
    const int g = lane >> 2, tg = lane & 3;
    const int b = blockIdx.x / HH, h = blockIdx.x % HH;
    const int q0 = blockIdx.y * 128;
    const float* base = g_qkv + (size_t)b * SEQ * C3;
    const float* kvb = base + CC + h * DH;

    uint32_t smb;
    asm("{ .reg .u64 t; cvta.to.shared.u64 t, %1; cvt.u32.u64 %0, t; }"
        : "=r"(smb) : "l"(sm));

    // ---- stage Q (prescaled, tf32) in Ks area; build fragments ----
    {
        const float* Qg = base + (size_t)q0 * C3 + h * DH;
        #pragma unroll
        for (int i = 0; i < 8; i++) {
            const int idx = tid + i * 256;
            const int r = idx >> 4, c = (idx & 15) * 4;
            float4 v = *(const float4*)(Qg + (size_t)r * C3 + c);
            float* d = sm + r * KS_LD + c;
            d[0] = tf32r(QSCALE * v.x);
            d[1] = tf32r(QSCALE * v.y);
            d[2] = tf32r(QSCALE * v.z);
            d[3] = tf32r(QSCALE * v.w);
        }
    }
    __syncthreads();
    uint32_t qf[8][4];
    {
        const float* Qs = sm + (wid * 16) * KS_LD;
        #pragma unroll
        for (int kk = 0; kk < 8; kk++) {
            qf[kk][0] = __float_as_uint(Qs[g * KS_LD + kk * 8 + tg]);
            qf[kk][1] = __float_as_uint(Qs[(g + 8) * KS_LD + kk * 8 + tg]);
            qf[kk][2] = __float_as_uint(Qs[g * KS_LD + kk * 8 + tg + 4]);
            qf[kk][3] = __float_as_uint(Qs[(g + 8) * KS_LD + kk * 8 + tg + 4]);
        }
    }
    __syncthreads();

    // prefetch mapping: row pr (0..63), float-col pc (0/16/32/48)
    const int pr = tid >> 2;
    const int pc = (tid & 3) * 16;

#define AISSUE(itt, pp) do {                                                  \
    const float* src_ = kvb + (size_t)((itt) * 64 + pr) * C3 + pc;            \
    const uint32_t kd_ = smb + (uint32_t)((pp) * 4352 + pr * KS_LD + pc) * 4u;\
    const uint32_t vd_ = smb + (uint32_t)(8704 + (pp) * 4608 + pr * VS_LD + pc) * 4u; \
    _Pragma("unroll")                                                         \
    for (int j_ = 0; j_ < 4; j_++) {                                          \
        asm volatile("cp.async.cg.shared.global [%0], [%1], 16;"              \
                     :: "r"(kd_ + j_ * 16), "l"(src_ + j_ * 4));              \
        asm volatile("cp.async.cg.shared.global [%0], [%1], 16;"              \
                     :: "r"(vd_ + j_ * 16), "l"(src_ + CC + j_ * 4));         \
    }                                                                         \
    asm volatile("cp.async.commit_group;");                                   \
} while (0)

    AISSUE(0, 0);

    float O[8][4];
    #pragma unroll
    for (int u = 0; u < 8; u++) { O[u][0] = O[u][1] = O[u][2] = O[u][3] = 0.f; }
    float m0 = -1e30f, m1 = -1e30f, l0 = 0.f, l1 = 0.f;

    const int sA = (lane & ~3) | (tg >> 1);
    const bool odd = (tg & 1);

    for (int it = 0; it < SEQ / 64; it++) {
        const int p = it & 1;
        asm volatile("cp.async.wait_group 0;" ::: "memory");
        __syncthreads();
        if (it + 1 < SEQ / 64) AISSUE(it + 1, p ^ 1);

        const float* Kb = sm + p * 4352;
        const float* Vb = sm + 8704 + p * 4608;

        // ---- S = Q K^T (tf32 cvt at K fragment load) ----
        float S[8][4];
        #pragma unroll
        for (int t = 0; t < 8; t++) {
            S[t][0] = S[t][1] = S[t][2] = S[t][3] = 0.f;
            const float* kr = Kb + (t * 8 + g) * KS_LD;
            #pragma unroll
            for (int kk = 0; kk < 8; kk++) {
                uint32_t bf[2];
                bf[0] = tf32u(kr[kk * 8 + tg]);
                bf[1] = tf32u(kr[kk * 8 + tg + 4]);
                MMA_TF32(S[t], qf[kk], bf);
            }
        }
        // ---- online softmax (base-2) ----
        float mx0 = -1e30f, mx1 = -1e30f;
        #pragma unroll
        for (int t = 0; t < 8; t++) {
            mx0 = fmaxf(mx0, fmaxf(S[t][0], S[t][1]));
            mx1 = fmaxf(mx1, fmaxf(S[t][2], S[t][3]));
        }
        mx0 = fmaxf(mx0, __shfl_xor_sync(0xffffffffu, mx0, 1));
        mx0 = fmaxf(mx0, __shfl_xor_sync(0xffffffffu, mx0, 2));
        mx1 = fmaxf(mx1, __shfl_xor_sync(0xffffffffu, mx1, 1));
        mx1 = fmaxf(mx1, __shfl_xor_sync(0xffffffffu, mx1, 2));
        const float n0 = fmaxf(m0, mx0), n1 = fmaxf(m1, mx1);
        const float c0 = exp2f(m0 - n0), c1 = exp2f(m1 - n1);
        m0 = n0; m1 = n1;
        #pragma unroll
        for (int u = 0; u < 8; u++) {
            O[u][0] *= c0; O[u][1] *= c0; O[u][2] *= c1; O[u][3] *= c1;
        }
        float s0 = 0.f, s1 = 0.f;
        // ---- per 8-key group: exp -> shuffle-route -> MMA into O ----
        #pragma unroll
        for (int t = 0; t < 8; t++) {
            const float e0 = exp2f(S[t][0] - n0), e1 = exp2f(S[t][1] - n0);
            const float e2 = exp2f(S[t][2] - n1), e3 = exp2f(S[t][3] - n1);
            s0 += e0 + e1; s1 += e2 + e3;
            const uint32_t p0 = tf32u(e0), p1 = tf32u(e1);
            const uint32_t p2 = tf32u(e2), p3 = tf32u(e3);
            const uint32_t x0 = __shfl_sync(0xffffffffu, p0, sA);
            const uint32_t x1 = __shfl_sync(0xffffffffu, p1, sA);
            const uint32_t x2 = __shfl_sync(0xffffffffu, p2, sA);
            const uint32_t x3 = __shfl_sync(0xffffffffu, p3, sA);
            const uint32_t y0 = __shfl_sync(0xffffffffu, p0, sA + 2);
            const uint32_t y1 = __shfl_sync(0xffffffffu, p1, sA + 2);
            const uint32_t y2 = __shfl_sync(0xffffffffu, p2, sA + 2);
            const uint32_t y3 = __shfl_sync(0xffffffffu, p3, sA + 2);
            uint32_t af[4];
            af[0] = odd ? x1 : x0;
            af[1] = odd ? x3 : x2;
            af[2] = odd ? y1 : y0;
            af[3] = odd ? y3 : y2;
            const float* vr0 = Vb + (t * 8 + tg) * VS_LD;
            const float* vr1 = Vb + (t * 8 + tg + 4) * VS_LD;
            #pragma unroll
            for (int u = 0; u < 8; u++) {
                uint32_t bf[2];
                bf[0] = tf32u(vr0[u * 8 + g]);
                bf[1] = tf32u(vr1[u * 8 + g]);
                MMA_TF32(O[u], af, bf);
            }
        }
        l0 = l0 * c0 + s0; l1 = l1 * c1 + s1;
    }

    // epilogue
    l0 += __shfl_xor_sync(0xffffffffu, l0, 1);
    l0 += __shfl_xor_sync(0xffffffffu, l0, 2);
    l1 += __shfl_xor_sync(0xffffffffu, l1, 1);
    l1 += __shfl_xor_sync(0xffffffffu, l1, 2);
    const float i0 = 1.f / l0, i1 = 1.f / l1;
    const int r0 = q0 + wid * 16 + g;
    float* o0 = g_att + (size_t)(b * SEQ + r0) * CC + h * DH;
    float* o1 = o0 + (size_t)8 * CC;
    #pragma unroll
    for (int u = 0; u < 8; u++) {
        float2 v0, v1;
        v0.x = O[u][0] * i0; v0.y = O[u][1] * i0;
        v1.x = O[u][2] * i1; v1.y = O[u][3] * i1;
        *(float2*)(o0 + u * 8 + 2 * tg) = v0;
        *(float2*)(o1 + u * 8 + 2 * tg) = v1;
    }
}

// ---------------------------------------------------------------------------
extern "C" void kernel_launch(void* const* d_in, const int* in_sizes, int n_in,
                              void* d_out, int out_size)
{
    const float* x      = (const float*)d_in[0];
    const float* cosb   = (const float*)d_in[1];
    const float* sinb   = (const float*)d_in[2];
    const float* qkv_w  = (const float*)d_in[3];
    const float* qkv_b  = (const float*)d_in[4];
    const float* proj_w = (const float*)d_in[5];
    const float* proj_b = (const float*)d_in[6];
    const float* qn_w   = (const float*)d_in[7];
    const float* kn_w   = (const float*)d_in[8];
    float* out = (float*)d_out;

    float* qkv; cudaGetSymbolAddress((void**)&qkv, g_qkv);
    float* att; cudaGetSymbolAddress((void**)&att, g_att);

    static int smem_set = 0;
    if (!smem_set) {
        cudaFuncSetAttribute(gemm_mma, cudaFuncAttributeMaxDynamicSharedMemorySize,
                             GEMM_SMEM);
        cudaFuncSetAttribute(flash_mma, cudaFuncAttributeMaxDynamicSharedMemorySize,
                             ATT_SMEM);
        smem_set = 1;
    }

    // 1) qkv = x @ qkv_w + qkv_b
    {
        dim3 grid(C3 / 128, MM / 128);
        gemm_mma<<<grid, 256, GEMM_SMEM>>>(x, qkv_w, qkv_b, qkv, C3, CC);
    }
    // 2) RMSNorm + RoPE on q,k (in place)
    {
        const int rows = 2 * MM * HH;
        rmsnorm_rope<<<rows / 8, 256>>>(cosb, sinb, qn_w, kn_w);
    }
    // 3) attention — tf32 mma.sync flash
    {
        dim3 grid(Bz * HH, SEQ / 128);
        flash_mma<<<grid, 256, ATT_SMEM>>>();
    }
    // 4) out = att @ proj_w + proj_b
    {
        dim3 grid(CC / 128, MM / 128);
        gemm_mma<<<grid, 256, GEMM_SMEM>>>(att, proj_w, proj_b, out, CC, CC);
    }
}

// round 7
// speedup vs baseline: 4.3815x; 1.1293x over previous
#include <cuda_runtime.h>
#include <cuda_bf16.h>
#include <cstdint>

// Problem constants
#define Bz   2
#define SEQ  2048
#define CC   768
#define HH   12
#define DH   64
#define MM   (Bz*SEQ)        // 4096
#define C3   (3*CC)          // 2304

// Scratch (no cudaMalloc allowed)
__device__ float g_qkv[(size_t)MM * C3];   // [B*N, 3*C]
__device__ float g_att[(size_t)MM * CC];   // attention output [B*N, C]
__device__ float g_xr [(size_t)MM * CC];   // tf32-rounded x
__device__ float g_w  [(size_t)CC * C3];   // tf32-rounded weights (reused)

__device__ __forceinline__ float tf32r(float x) {
    float o;
    asm("cvt.rna.tf32.f32 %0, %1;" : "=f"(o) : "f"(x));
    return o;
}
__device__ __forceinline__ uint32_t tf32u(float x) {
    float o;
    asm("cvt.rna.tf32.f32 %0, %1;" : "=f"(o) : "f"(x));
    return __float_as_uint(o);
}

#define MMA_TF32(d, a, b)                                                     \
    asm volatile("mma.sync.aligned.m16n8k8.row.col.f32.tf32.tf32.f32 "        \
        "{%0,%1,%2,%3}, {%4,%5,%6,%7}, {%8,%9}, {%0,%1,%2,%3};"               \
        : "+f"((d)[0]), "+f"((d)[1]), "+f"((d)[2]), "+f"((d)[3])              \
        : "r"((a)[0]), "r"((a)[1]), "r"((a)[2]), "r"((a)[3]),                 \
          "r"((b)[0]), "r"((b)[1]))

// ---------------------------------------------------------------------------
// Streaming tf32 rounding: dst[i] = tf32(src[i]).  n % 4 == 0.
// ---------------------------------------------------------------------------
__global__ __launch_bounds__(256) void round_tf32(
    const float* __restrict__ src, float* __restrict__ dst, int n4)
{
    const int i = blockIdx.x * blockDim.x + threadIdx.x;
    if (i < n4) {
        float4 v = *(const float4*)(src + 4 * (size_t)i);
        v.x = tf32r(v.x); v.y = tf32r(v.y);
        v.z = tf32r(v.z); v.w = tf32r(v.w);
        *(float4*)(dst + 4 * (size_t)i) = v;
    }
}

// ---------------------------------------------------------------------------
// tf32 mma.sync GEMM, cp.async 3-stage, one sync per chunk.
// Inputs MUST be pre-rounded to tf32. round_out=1 rounds the stored output.
// ---------------------------------------------------------------------------
#define AS_LD   36
#define BS_LD   136
#define BUF_F   (128*AS_LD + 32*BS_LD)      // 8960 floats
#define GEMM_SMEM (3 * BUF_F * 4)           // 107520 bytes

__global__ __launch_bounds__(256, 2) void gemm_mma(
    const float* __restrict__ A, const float* __restrict__ Bw,
    const float* __restrict__ bias, float* __restrict__ Cm,
    int Nn, int K, int round_out)
{
    extern __shared__ float smem[];
    uint32_t smb;
    asm("{ .reg .u64 t; cvta.to.shared.u64 t, %1; cvt.u32.u64 %0, t; }"
        : "=r"(smb) : "l"(smem));
    const int tid = threadIdx.x;
    const int wid = tid >> 5;
    const int lane = tid & 31;
    const int g  = lane >> 2;
    const int tg = lane & 3;
    const int wr = wid >> 2;
    const int wc = wid & 3;
    const int row0 = blockIdx.y * 128, col0 = blockIdx.x * 128;

    const int aRowB = tid >> 3;
    const int aCol4 = tid & 7;
    const int bRowB = tid >> 5;
    const int bCol4 = tid & 31;

    float acc[4][4][4];
    #pragma unroll
    for (int mt = 0; mt < 4; mt++)
        #pragma unroll
        for (int nt = 0; nt < 4; nt++)
            #pragma unroll
            for (int r = 0; r < 4; r++) acc[mt][nt][r] = 0.f;

    const int chunks = K / 32;

#define GISSUE(cc, pp) do {                                                   \
    const int k0_ = (cc) * 32;                                                \
    _Pragma("unroll")                                                         \
    for (int i_ = 0; i_ < 4; i_++) {                                          \
        const float* as_ = A + (size_t)(row0 + aRowB + 32 * i_) * K + k0_ + aCol4 * 4; \
        const uint32_t ad_ = smb + (uint32_t)((pp) * BUF_F + (aRowB + 32 * i_) * AS_LD + aCol4 * 4) * 4u; \
        asm volatile("cp.async.cg.shared.global [%0], [%1], 16;" :: "r"(ad_), "l"(as_)); \
        const float* bs_ = Bw + (size_t)(k0_ + bRowB + 8 * i_) * Nn + col0 + bCol4 * 4; \
        const uint32_t bd_ = smb + (uint32_t)((pp) * BUF_F + 128 * AS_LD + (bRowB + 8 * i_) * BS_LD + bCol4 * 4) * 4u; \
        asm volatile("cp.async.cg.shared.global [%0], [%1], 16;" :: "r"(bd_), "l"(bs_)); \
    }                                                                         \
    asm volatile("cp.async.commit_group;");                                   \
} while (0)

    GISSUE(0, 0);
    GISSUE(1, 1);

    for (int c = 0; c < chunks; c++) {
        if (c + 1 < chunks) {
            asm volatile("cp.async.wait_group 1;" ::: "memory");
        } else {
            asm volatile("cp.async.wait_group 0;" ::: "memory");
        }
        __syncthreads();
        if (c + 2 < chunks) GISSUE(c + 2, (c + 2) % 3);

        const float* As = smem + (c % 3) * BUF_F;
        const float* Bs = As + 128 * AS_LD;
        #pragma unroll
        for (int kk = 0; kk < 32; kk += 8) {
            uint32_t af[4][4], bf[4][2];
            #pragma unroll
            for (int mt = 0; mt < 4; mt++) {
                const int m = wr * 64 + mt * 16 + g;
                af[mt][0] = __float_as_uint(As[m * AS_LD + kk + tg]);
                af[mt][1] = __float_as_uint(As[(m + 8) * AS_LD + kk + tg]);
                af[mt][2] = __float_as_uint(As[m * AS_LD + kk + tg + 4]);
                af[mt][3] = __float_as_uint(As[(m + 8) * AS_LD + kk + tg + 4]);
            }
            #pragma unroll
            for (int nt = 0; nt < 4; nt++) {
                const int n = wc * 32 + nt * 8 + g;
                bf[nt][0] = __float_as_uint(Bs[(kk + tg) * BS_LD + n]);
                bf[nt][1] = __float_as_uint(Bs[(kk + tg + 4) * BS_LD + n]);
            }
            #pragma unroll
            for (int mt = 0; mt < 4; mt++)
                #pragma unroll
                for (int nt = 0; nt < 4; nt++)
                    MMA_TF32(acc[mt][nt], af[mt], bf[nt]);
        }
    }

    #pragma unroll
    for (int mt = 0; mt < 4; mt++) {
        const int r0 = row0 + wr * 64 + mt * 16 + g;
        #pragma unroll
        for (int nt = 0; nt < 4; nt++) {
            const int cc = col0 + wc * 32 + nt * 8 + 2 * tg;
            const float b0 = __ldg(bias + cc), b1 = __ldg(bias + cc + 1);
            float2 v0, v1;
            v0.x = acc[mt][nt][0] + b0; v0.y = acc[mt][nt][1] + b1;
            v1.x = acc[mt][nt][2] + b0; v1.y = acc[mt][nt][3] + b1;
            if (round_out) {
                v0.x = tf32r(v0.x); v0.y = tf32r(v0.y);
                v1.x = tf32r(v1.x); v1.y = tf32r(v1.y);
            }
            *(float2*)(Cm + (size_t)r0 * Nn + cc) = v0;
            *(float2*)(Cm + (size_t)(r0 + 8) * Nn + cc) = v1;
        }
    }
}

// ---------------------------------------------------------------------------
// Fused RMSNorm + RoPE; outputs tf32-rounded (consumed only by flash MMAs).
// ---------------------------------------------------------------------------
__global__ __launch_bounds__(256) void rmsnorm_rope(
    const float* __restrict__ cosb, const float* __restrict__ sinb,
    const float* __restrict__ qn_w, const float* __restrict__ kn_w)
{
    const int warp = (blockIdx.x * blockDim.x + threadIdx.x) >> 5;
    const int lane = threadIdx.x & 31;
    const int which = warp & 1;
    const int h     = (warp >> 1) % HH;
    const int bn    = warp / (2 * HH);
    const int n     = bn & (SEQ - 1);

    const float* w = which ? kn_w : qn_w;
    float* p = g_qkv + (size_t)bn * C3 + which * CC + h * DH;

    float2 v = *(float2*)(p + 2 * lane);
    float ss = v.x * v.x + v.y * v.y;
    #pragma unroll
    for (int o = 16; o; o >>= 1) ss += __shfl_xor_sync(0xffffffffu, ss, o);
    const float inv = rsqrtf(ss * (1.0f / (float)DH) + 1e-6f);

    float x0 = v.x * inv * w[2 * lane];
    float x1 = v.y * inv * w[2 * lane + 1];
    const float c = cosb[n * (DH / 2) + lane];
    const float s = sinb[n * (DH / 2) + lane];
    float2 r;
    r.x = tf32r(x0 * c - x1 * s);
    r.y = tf32r(x0 * s + x1 * c);
    *(float2*)(p + 2 * lane) = r;
}

// ---------------------------------------------------------------------------
// Flash attention, tf32 mma.sync. K/V/Q pre-rounded -> no cvt in mainloop.
// smem floats: Ks[2][64][68] @0, Vs[2][64][72] @8704.
// ---------------------------------------------------------------------------
#define KS_LD 68
#define VS_LD 72
#define ATT_SMEM (17920 * 4)              // 71680 bytes
#define QSCALE   (0.125f * 1.44269504f)   // Dh^-0.5 * log2(e)

__global__ __launch_bounds__(256, 2) void flash_mma()
{
    extern __shared__ float sm[];
    const int tid = threadIdx.x;
    const int lane = tid & 31, wid = tid >> 5;
    const int g = lane >> 2, tg = lane & 3;
    const int b = blockIdx.x / HH, h = blockIdx.x % HH;
    const int q0 = blockIdx.y * 128;
    const float* base = g_qkv + (size_t)b * SEQ * C3;
    const float* kvb = base + CC + h * DH;

    uint32_t smb;
    asm("{ .reg .u64 t; cvta.to.shared.u64 t, %1; cvt.u32.u64 %0, t; }"
        : "=r"(smb) : "l"(sm));

    // ---- stage Q (prescaled, tf32) ----
    {
        const float* Qg = base + (size_t)q0 * C3 + h * DH;
        #pragma unroll
        for (int i = 0; i < 8; i++) {
            const int idx = tid + i * 256;
            const int r = idx >> 4, c = (idx & 15) * 4;
            float4 v = *(const float4*)(Qg + (size_t)r * C3 + c);
            float* d = sm + r * KS_LD + c;
            d[0] = tf32r(QSCALE * v.x);
            d[1] = tf32r(QSCALE * v.y);
            d[2] = tf32r(QSCALE * v.z);
            d[3] = tf32r(QSCALE * v.w);
        }
    }
    __syncthreads();
    uint32_t qf[8][4];
    {
        const float* Qs = sm + (wid * 16) * KS_LD;
        #pragma unroll
        for (int kk = 0; kk < 8; kk++) {
            qf[kk][0] = __float_as_uint(Qs[g * KS_LD + kk * 8 + tg]);
            qf[kk][1] = __float_as_uint(Qs[(g + 8) * KS_LD + kk * 8 + tg]);
            qf[kk][2] = __float_as_uint(Qs[g * KS_LD + kk * 8 + tg + 4]);
            qf[kk][3] = __float_as_uint(Qs[(g + 8) * KS_LD + kk * 8 + tg + 4]);
        }
    }
    __syncthreads();

    const int pr = tid >> 2;
    const int pc = (tid & 3) * 16;

#define AISSUE(itt, pp) do {                                                  \
    const float* src_ = kvb + (size_t)((itt) * 64 + pr) * C3 + pc;            \
    const uint32_t kd_ = smb + (uint32_t)((pp) * 4352 + pr * KS_LD + pc) * 4u;\
    const uint32_t vd_ = smb + (uint32_t)(8704 + (pp) * 4608 + pr * VS_LD + pc) * 4u; \
    _Pragma("unroll")                                                         \
    for (int j_ = 0; j_ < 4; j_++) {                                          \
        asm volatile("cp.async.cg.shared.global [%0], [%1], 16;"              \
                     :: "r"(kd_ + j_ * 16), "l"(src_ + j_ * 4));              \
        asm volatile("cp.async.cg.shared.global [%0], [%1], 16;"              \
                     :: "r"(vd_ + j_ * 16), "l"(src_ + CC + j_ * 4));         \
    }                                                                         \
    asm volatile("cp.async.commit_group;");                                   \
} while (0)

    AISSUE(0, 0);

    float O[8][4];
    #pragma unroll
    for (int u = 0; u < 8; u++) { O[u][0] = O[u][1] = O[u][2] = O[u][3] = 0.f; }
    float m0 = -1e30f, m1 = -1e30f, l0 = 0.f, l1 = 0.f;

    const int sA = (lane & ~3) | (tg >> 1);
    const bool odd = (tg & 1);

    for (int it = 0; it < SEQ / 64; it++) {
        const int p = it & 1;
        asm volatile("cp.async.wait_group 0;" ::: "memory");
        __syncthreads();
        if (it + 1 < SEQ / 64) AISSUE(it + 1, p ^ 1);

        const float* Kb = sm + p * 4352;
        const float* Vb = sm + 8704 + p * 4608;

        // ---- S = Q K^T ----
        float S[8][4];
        #pragma unroll
        for (int t = 0; t < 8; t++) {
            S[t][0] = S[t][1] = S[t][2] = S[t][3] = 0.f;
            const float* kr = Kb + (t * 8 + g) * KS_LD;
            #pragma unroll
            for (int kk = 0; kk < 8; kk++) {
                uint32_t bf[2];
                bf[0] = __float_as_uint(kr[kk * 8 + tg]);
                bf[1] = __float_as_uint(kr[kk * 8 + tg + 4]);
                MMA_TF32(S[t], qf[kk], bf);
            }
        }
        // ---- online softmax (base-2) ----
        float mx0 = -1e30f, mx1 = -1e30f;
        #pragma unroll
        for (int t = 0; t < 8; t++) {
            mx0 = fmaxf(mx0, fmaxf(S[t][0], S[t][1]));
            mx1 = fmaxf(mx1, fmaxf(S[t][2], S[t][3]));
        }
        mx0 = fmaxf(mx0, __shfl_xor_sync(0xffffffffu, mx0, 1));
        mx0 = fmaxf(mx0, __shfl_xor_sync(0xffffffffu, mx0, 2));
        mx1 = fmaxf(mx1, __shfl_xor_sync(0xffffffffu, mx1, 1));
        mx1 = fmaxf(mx1, __shfl_xor_sync(0xffffffffu, mx1, 2));
        const float n0 = fmaxf(m0, mx0), n1 = fmaxf(m1, mx1);
        const float c0 = exp2f(m0 - n0), c1 = exp2f(m1 - n1);
        m0 = n0; m1 = n1;
        #pragma unroll
        for (int u = 0; u < 8; u++) {
            O[u][0] *= c0; O[u][1] *= c0; O[u][2] *= c1; O[u][3] *= c1;
        }
        float s0 = 0.f, s1 = 0.f;
        #pragma unroll
        for (int t = 0; t < 8; t++) {
            const float e0 = exp2f(S[t][0] - n0), e1 = exp2f(S[t][1] - n0);
            const float e2 = exp2f(S[t][2] - n1), e3 = exp2f(S[t][3] - n1);
            s0 += e0 + e1; s1 += e2 + e3;
            const uint32_t p0 = tf32u(e0), p1 = tf32u(e1);
            const uint32_t p2 = tf32u(e2), p3 = tf32u(e3);
            const uint32_t x0 = __shfl_sync(0xffffffffu, p0, sA);
            const uint32_t x1 = __shfl_sync(0xffffffffu, p1, sA);
            const uint32_t x2 = __shfl_sync(0xffffffffu, p2, sA);
            const uint32_t x3 = __shfl_sync(0xffffffffu, p3, sA);
            const uint32_t y0 = __shfl_sync(0xffffffffu, p0, sA + 2);
            const uint32_t y1 = __shfl_sync(0xffffffffu, p1, sA + 2);
            const uint32_t y2 = __shfl_sync(0xffffffffu, p2, sA + 2);
            const uint32_t y3 = __shfl_sync(0xffffffffu, p3, sA + 2);
            uint32_t af[4];
            af[0] = odd ? x1 : x0;
            af[1] = odd ? x3 : x2;
            af[2] = odd ? y1 : y0;
            af[3] = odd ? y3 : y2;
            const float* vr0 = Vb + (t * 8 + tg) * VS_LD;
            const float* vr1 = Vb + (t * 8 + tg + 4) * VS_LD;
            #pragma unroll
            for (int u = 0; u < 8; u++) {
                uint32_t bf[2];
                bf[0] = __float_as_uint(vr0[u * 8 + g]);
                bf[1] = __float_as_uint(vr1[u * 8 + g]);
                MMA_TF32(O[u], af, bf);
            }
        }
        l0 = l0 * c0 + s0; l1 = l1 * c1 + s1;
    }

    // epilogue: normalize, round to tf32 (feeds proj GEMM), store
    l0 += __shfl_xor_sync(0xffffffffu, l0, 1);
    l0 += __shfl_xor_sync(0xffffffffu, l0, 2);
    l1 += __shfl_xor_sync(0xffffffffu, l1, 1);
    l1 += __shfl_xor_sync(0xffffffffu, l1, 2);
    const float i0 = 1.f / l0, i1 = 1.f / l1;
    const int r0 = q0 + wid * 16 + g;
    float* o0 = g_att + (size_t)(b * SEQ + r0) * CC + h * DH;
    float* o1 = o0 + (size_t)8 * CC;
    #pragma unroll
    for (int u = 0; u < 8; u++) {
        float2 v0, v1;
        v0.x = tf32r(O[u][0] * i0); v0.y = tf32r(O[u][1] * i0);
        v1.x = tf32r(O[u][2] * i1); v1.y = tf32r(O[u][3] * i1);
        *(float2*)(o0 + u * 8 + 2 * tg) = v0;
        *(float2*)(o1 + u * 8 + 2 * tg) = v1;
    }
}

// ---------------------------------------------------------------------------
extern "C" void kernel_launch(void* const* d_in, const int* in_sizes, int n_in,
                              void* d_out, int out_size)
{
    const float* x      = (const float*)d_in[0];
    const float* cosb   = (const float*)d_in[1];
    const float* sinb   = (const float*)d_in[2];
    const float* qkv_w  = (const float*)d_in[3];
    const float* qkv_b  = (const float*)d_in[4];
    const float* proj_w = (const float*)d_in[5];
    const float* proj_b = (const float*)d_in[6];
    const float* qn_w   = (const float*)d_in[7];
    const float* kn_w   = (const float*)d_in[8];
    float* out = (float*)d_out;

    float* qkv; cudaGetSymbolAddress((void**)&qkv, g_qkv);
    float* att; cudaGetSymbolAddress((void**)&att, g_att);
    float* xr;  cudaGetSymbolAddress((void**)&xr,  g_xr);
    float* wbuf; cudaGetSymbolAddress((void**)&wbuf, g_w);

    static int smem_set = 0;
    if (!smem_set) {
        cudaFuncSetAttribute(gemm_mma, cudaFuncAttributeMaxDynamicSharedMemorySize,
                             GEMM_SMEM);
        cudaFuncSetAttribute(flash_mma, cudaFuncAttributeMaxDynamicSharedMemorySize,
                             ATT_SMEM);
        smem_set = 1;
    }

    // 0) pre-round inputs to tf32
    round_tf32<<<(MM * CC / 4 + 255) / 256, 256>>>(x, xr, MM * CC / 4);
    round_tf32<<<(CC * C3 / 4 + 255) / 256, 256>>>(qkv_w, wbuf, CC * C3 / 4);

    // 1) qkv = xr @ w + qkv_b (rounded output: K,V pre-rounded at source)
    {
        dim3 grid(C3 / 128, MM / 128);
        gemm_mma<<<grid, 256, GEMM_SMEM>>>(xr, wbuf, qkv_b, qkv, C3, CC, 1);
    }
    // 2) RMSNorm + RoPE on q,k (in place, rounded output)
    {
        const int rows = 2 * MM * HH;
        rmsnorm_rope<<<rows / 8, 256>>>(cosb, sinb, qn_w, kn_w);
    }
    // 3) attention
    {
        dim3 grid(Bz * HH, SEQ / 128);
        flash_mma<<<grid, 256, ATT_SMEM>>>();
    }
    // 4) out = att @ proj_w + proj_b  (no output rounding)
    round_tf32<<<(CC * CC / 4 + 255) / 256, 256>>>(proj_w, wbuf, CC * CC / 4);
    {
        dim3 grid(CC / 128, MM / 128);
        gemm_mma<<<grid, 256, GEMM_SMEM>>>(att, wbuf, proj_b, out, CC, CC, 0);
    }
}